// round 1
// baseline (speedup 1.0000x reference)
#include <cuda_runtime.h>
#include <cstdint>

// Problem dims (fixed by the dataset)
#define BB 4
#define NN 4096
#define DD 256

// ---------------- device scratch (allocation-free rule: __device__ globals) --
__device__ float g_h[BB * NN * DD];       // h = feat @ W   (64 MB)
__device__ float g_Ax[BB * NN];
__device__ float g_Ay[BB * NN];
__device__ unsigned int g_maxAxEnc[BB];   // order-preserving encoded float max

// ---------------- helpers ----------------------------------------------------
static __device__ __forceinline__ unsigned enc_f(float f) {
    unsigned u = __float_as_uint(f);
    return (u & 0x80000000u) ? ~u : (u | 0x80000000u);
}
static __device__ __forceinline__ float dec_f(unsigned e) {
    return (e & 0x80000000u) ? __uint_as_float(e & 0x7fffffffu)
                             : __uint_as_float(~e);
}
// duplicate one fp32 into both halves of a packed f32x2
static __device__ __forceinline__ unsigned long long pack2(float x) {
    unsigned long long r;
    asm("mov.b64 %0, {%1, %1};" : "=l"(r) : "f"(x));
    return r;
}
static __device__ __forceinline__ unsigned long long fma2(
    unsigned long long a, unsigned long long b, unsigned long long c) {
    unsigned long long d;
    asm("fma.rn.f32x2 %0, %1, %2, %3;" : "=l"(d) : "l"(a), "l"(b), "l"(c));
    return d;
}
static __device__ __forceinline__ void unpack2(unsigned long long v, float& lo, float& hi) {
    asm("mov.b64 {%0, %1}, %2;" : "=f"(lo), "=f"(hi) : "l"(v));
}

// ---------------- kernel 0: init maxAx accumulators --------------------------
__global__ void k_init() {
    if (threadIdx.x < BB) g_maxAxEnc[threadIdx.x] = 0u;
}

// ---------------- kernel 1: h = feat @ W  ([16384,256] x [256,256]) ----------
// CTA: 64 rows x 256 cols, 256 threads, thread tile 8 rows x 8 cols.
// Accumulate in packed f32x2 over row-pairs.
__global__ void __launch_bounds__(256, 2) k_h(const float* __restrict__ feat,
                                              const float* __restrict__ W) {
    __shared__ float fT[32 * 64];    // [k][row]  transposed feat tile
    __shared__ float Ws[32 * 256];   // [k][col]  W tile

    const int t  = threadIdx.x;
    const int ty = t >> 5;           // 0..7  -> row group (ty*8)
    const int tx = t & 31;           // 0..31 -> col group (tx*4 and 128+tx*4)
    const int r0 = blockIdx.x * 64;

    unsigned long long acc[4][8];
#pragma unroll
    for (int i = 0; i < 4; i++)
#pragma unroll
        for (int j = 0; j < 8; j++) acc[i][j] = 0ull;

    for (int kt = 0; kt < 8; kt++) {
        const int k0 = kt * 32;
        // stage feat tile (transposed)
        {
            const int rr = t >> 2;
            const int kq = (t & 3) * 8;
            const float* fp = feat + (size_t)(r0 + rr) * DD + k0 + kq;
            float4 f0 = *(const float4*)fp;
            float4 f1 = *(const float4*)(fp + 4);
            fT[(kq + 0) * 64 + rr] = f0.x;  fT[(kq + 1) * 64 + rr] = f0.y;
            fT[(kq + 2) * 64 + rr] = f0.z;  fT[(kq + 3) * 64 + rr] = f0.w;
            fT[(kq + 4) * 64 + rr] = f1.x;  fT[(kq + 5) * 64 + rr] = f1.y;
            fT[(kq + 6) * 64 + rr] = f1.z;  fT[(kq + 7) * 64 + rr] = f1.w;
        }
        // stage W tile
        {
            const int kk = t >> 3;
            const int c0 = (t & 7) * 32;
            const float* wp = W + (size_t)(k0 + kk) * DD + c0;
#pragma unroll
            for (int u = 0; u < 8; u++)
                *(float4*)&Ws[kk * 256 + c0 + u * 4] = *(const float4*)(wp + u * 4);
        }
        __syncthreads();
#pragma unroll 4
        for (int k = 0; k < 32; k++) {
            ulonglong2 A0 = *(const ulonglong2*)&fT[k * 64 + ty * 8];
            ulonglong2 A1 = *(const ulonglong2*)&fT[k * 64 + ty * 8 + 4];
            float4 b0 = *(const float4*)&Ws[k * 256 + tx * 4];
            float4 b1 = *(const float4*)&Ws[k * 256 + 128 + tx * 4];
            unsigned long long bb[8];
            bb[0] = pack2(b0.x); bb[1] = pack2(b0.y); bb[2] = pack2(b0.z); bb[3] = pack2(b0.w);
            bb[4] = pack2(b1.x); bb[5] = pack2(b1.y); bb[6] = pack2(b1.z); bb[7] = pack2(b1.w);
            unsigned long long pp[4] = {A0.x, A0.y, A1.x, A1.y};
#pragma unroll
            for (int ii = 0; ii < 4; ii++)
#pragma unroll
                for (int dd = 0; dd < 8; dd++)
                    acc[ii][dd] = fma2(pp[ii], bb[dd], acc[ii][dd]);
        }
        __syncthreads();
    }
    // epilogue: write h
#pragma unroll
    for (int ii = 0; ii < 4; ii++) {
        const int re = r0 + ty * 8 + ii * 2;
        float ve[8], vo[8];
#pragma unroll
        for (int dd = 0; dd < 8; dd++) unpack2(acc[ii][dd], ve[dd], vo[dd]);
        float* pe = g_h + (size_t)re * DD;
        float* po = g_h + (size_t)(re + 1) * DD;
        *(float4*)(pe + tx * 4)       = make_float4(ve[0], ve[1], ve[2], ve[3]);
        *(float4*)(pe + 128 + tx * 4) = make_float4(ve[4], ve[5], ve[6], ve[7]);
        *(float4*)(po + tx * 4)       = make_float4(vo[0], vo[1], vo[2], vo[3]);
        *(float4*)(po + 128 + tx * 4) = make_float4(vo[4], vo[5], vo[6], vo[7]);
    }
}

// ---------------- kernel 2: Ax = h@a1, Ay = h@a2, maxAx per batch ------------
__global__ void k_axy(const float* __restrict__ a1, const float* __restrict__ a2) {
    const int t   = threadIdx.x;
    const int row = blockIdx.x * 32 + (t >> 3);
    const int l8  = t & 7;
    const float* hr = g_h + (size_t)row * DD;
    float ax = 0.f, ay = 0.f;
#pragma unroll
    for (int it = 0; it < 8; it++) {
        const int c = l8 * 4 + it * 32;
        float4 h4 = *(const float4*)(hr + c);
        float4 A  = *(const float4*)(a1 + c);
        float4 Bv = *(const float4*)(a2 + c);
        ax += h4.x * A.x + h4.y * A.y + h4.z * A.z + h4.w * A.w;
        ay += h4.x * Bv.x + h4.y * Bv.y + h4.z * Bv.z + h4.w * Bv.w;
    }
#pragma unroll
    for (int off = 4; off; off >>= 1) {
        ax += __shfl_down_sync(0xffffffffu, ax, off);
        ay += __shfl_down_sync(0xffffffffu, ay, off);
    }
    if (l8 == 0) {
        g_Ax[row] = ax;
        g_Ay[row] = ay;
        atomicMax(&g_maxAxEnc[row >> 12], enc_f(ax));
    }
}

// ---------------- kernel 3: fused masked-softmax attention * h + elu ---------
// CTA: 64 i-rows of one batch. Loop over 32 j-tiles of 128.
// Phase 1: p-tile (exp(leaky(Ax_j+Ay_i) - M_i) masked by adj) -> smem (j-major).
// Phase 2: acc[i][d] += p * h  via packed f32x2, i-paired accumulators.
// Epilogue: divide by rowsum, elu, store.
__global__ void __launch_bounds__(256, 2) k_main(const int* __restrict__ adj,
                                                 float* __restrict__ out) {
    __shared__ float pT[128 * 68];   // [j][i], pad 68 to dodge bank conflicts
    __shared__ float Axs[128];
    __shared__ float Ays[64];
    __shared__ float Ms[64];
    __shared__ float ssm[64 * 4];

    const int t  = threadIdx.x;
    const int b  = blockIdx.y;
    const int i0 = blockIdx.x * 64;

    if (t < 64) {
        float ay = g_Ay[b * NN + i0 + t];
        Ays[t] = ay;
        Ms[t]  = fmaxf(0.f, dec_f(g_maxAxEnc[b]) + ay);
    }
    __syncthreads();

    // phase-1 mapping
    const int i1 = t >> 2;
    const int jc = (t & 3) * 32;
    const float ay_i = Ays[i1];
    const float M_i  = Ms[i1];
    // phase-2 mapping
    const int ty = t >> 5;
    const int tx = t & 31;

    unsigned long long acc[4][8];
#pragma unroll
    for (int i = 0; i < 4; i++)
#pragma unroll
        for (int j = 0; j < 8; j++) acc[i][j] = 0ull;
    float ssum = 0.f;

    const int* adjrow = adj + (size_t)b * NN * NN + (size_t)(i0 + i1) * NN + jc;

    for (int jt = 0; jt < 32; jt++) {
        const int j0 = jt * 128;
        if (t < 128) Axs[t] = g_Ax[b * NN + j0 + t];
        __syncthreads();

        // ---- phase 1: p tile ----
        const int4* ar = (const int4*)(adjrow + j0);
#pragma unroll
        for (int v = 0; v < 8; v++) {
            int4 a4 = ar[v];
            const int jj = jc + v * 4;
            {
                float s = Axs[jj] + ay_i;
                float e = (s > 0.f) ? s : 0.2f * s;
                float p = (a4.x > 0) ? __expf(e - M_i) : 0.f;
                ssum += p; pT[(jj + 0) * 68 + i1] = p;
            }
            {
                float s = Axs[jj + 1] + ay_i;
                float e = (s > 0.f) ? s : 0.2f * s;
                float p = (a4.y > 0) ? __expf(e - M_i) : 0.f;
                ssum += p; pT[(jj + 1) * 68 + i1] = p;
            }
            {
                float s = Axs[jj + 2] + ay_i;
                float e = (s > 0.f) ? s : 0.2f * s;
                float p = (a4.z > 0) ? __expf(e - M_i) : 0.f;
                ssum += p; pT[(jj + 2) * 68 + i1] = p;
            }
            {
                float s = Axs[jj + 3] + ay_i;
                float e = (s > 0.f) ? s : 0.2f * s;
                float p = (a4.w > 0) ? __expf(e - M_i) : 0.f;
                ssum += p; pT[(jj + 3) * 68 + i1] = p;
            }
        }
        __syncthreads();

        // ---- phase 2: acc += p @ h ----
        const float* hb = g_h + ((size_t)(b * NN + j0) << 8);
#pragma unroll 2
        for (int j = 0; j < 128; j++) {
            ulonglong2 P0 = *(const ulonglong2*)&pT[j * 68 + ty * 8];
            ulonglong2 P1 = *(const ulonglong2*)&pT[j * 68 + ty * 8 + 4];
            const float* hr = hb + ((size_t)j << 8);
            float4 h0 = *(const float4*)(hr + tx * 4);
            float4 h1 = *(const float4*)(hr + 128 + tx * 4);
            unsigned long long hh[8];
            hh[0] = pack2(h0.x); hh[1] = pack2(h0.y); hh[2] = pack2(h0.z); hh[3] = pack2(h0.w);
            hh[4] = pack2(h1.x); hh[5] = pack2(h1.y); hh[6] = pack2(h1.z); hh[7] = pack2(h1.w);
            unsigned long long pp[4] = {P0.x, P0.y, P1.x, P1.y};
#pragma unroll
            for (int ii = 0; ii < 4; ii++)
#pragma unroll
                for (int dd = 0; dd < 8; dd++)
                    acc[ii][dd] = fma2(pp[ii], hh[dd], acc[ii][dd]);
        }
        __syncthreads();
    }

    // ---- rowsum reduce + epilogue ----
    ssm[i1 * 4 + (t & 3)] = ssum;
    __syncthreads();
#pragma unroll
    for (int ii = 0; ii < 4; ii++) {
        const int ie = ty * 8 + ii * 2;
        float Se = ssm[ie * 4] + ssm[ie * 4 + 1] + ssm[ie * 4 + 2] + ssm[ie * 4 + 3];
        float So = ssm[(ie + 1) * 4] + ssm[(ie + 1) * 4 + 1] +
                   ssm[(ie + 1) * 4 + 2] + ssm[(ie + 1) * 4 + 3];
        float re = 1.f / Se, ro = 1.f / So;
        float ve[8], vo[8];
#pragma unroll
        for (int dd = 0; dd < 8; dd++) {
            float lo, hi;
            unpack2(acc[ii][dd], lo, hi);
            lo *= re; hi *= ro;
            ve[dd] = (lo > 0.f) ? lo : expm1f(lo);
            vo[dd] = (hi > 0.f) ? hi : expm1f(hi);
        }
        float* pe = out + ((size_t)(b * NN + i0 + ie) << 8);
        float* po = out + ((size_t)(b * NN + i0 + ie + 1) << 8);
        *(float4*)(pe + tx * 4)       = make_float4(ve[0], ve[1], ve[2], ve[3]);
        *(float4*)(pe + 128 + tx * 4) = make_float4(ve[4], ve[5], ve[6], ve[7]);
        *(float4*)(po + tx * 4)       = make_float4(vo[0], vo[1], vo[2], vo[3]);
        *(float4*)(po + 128 + tx * 4) = make_float4(vo[4], vo[5], vo[6], vo[7]);
    }
}

// ---------------- launch ------------------------------------------------------
extern "C" void kernel_launch(void* const* d_in, const int* in_sizes, int n_in,
                              void* d_out, int out_size) {
    const float* feat = (const float*)d_in[0];
    const int*   adj  = (const int*)d_in[1];
    const float* W    = (const float*)d_in[2];
    const float* a1   = (const float*)d_in[3];
    const float* a2   = (const float*)d_in[4];
    float* out = (float*)d_out;

    k_init<<<1, 32>>>();
    k_h<<<BB * NN / 64, 256>>>(feat, W);
    k_axy<<<BB * NN / 32, 256>>>(a1, a2);
    dim3 grid(NN / 64, BB);
    k_main<<<grid, 256>>>(adj, out);
}

// round 4
// speedup vs baseline: 1.9477x; 1.9477x over previous
#include <cuda_runtime.h>
#include <cuda_bf16.h>
#include <cstdint>

#define BB 4
#define NN 4096
#define DD 256
#define KC 64
#define NCHUNK (NN / KC)

// tcgen05 is arch-SPECIFIC (sm_103a). The harness also runs a plain
// compute_103 pass, so every tcgen05 use must be feature-guarded.
#if defined(__CUDA_ARCH_FEAT_SM103_ALL) || \
    (defined(__CUDA_ARCH_SPECIFIC__) && (__CUDA_ARCH_SPECIFIC__ == 1030)) || \
    defined(__CUDA_ARCH_FEAT_SM100_ALL)
#define HAS_TC 1
#else
#define HAS_TC 0
#endif

// ---------------- device scratch ---------------------------------------------
__device__ float g_h[BB * NN * DD];
__device__ float g_Ax[BB * NN];
__device__ float g_Ay[BB * NN];
__device__ unsigned int g_maxAxEnc[BB];

// ---------------- helpers ----------------------------------------------------
static __device__ __forceinline__ unsigned enc_f(float f) {
    unsigned u = __float_as_uint(f);
    return (u & 0x80000000u) ? ~u : (u | 0x80000000u);
}
static __device__ __forceinline__ float dec_f(unsigned e) {
    return (e & 0x80000000u) ? __uint_as_float(e & 0x7fffffffu)
                             : __uint_as_float(~e);
}
static __device__ __forceinline__ unsigned long long pack2(float x) {
    unsigned long long r;
    asm("mov.b64 %0, {%1, %1};" : "=l"(r) : "f"(x));
    return r;
}
static __device__ __forceinline__ unsigned long long fma2(
    unsigned long long a, unsigned long long b, unsigned long long c) {
    unsigned long long d;
    asm("fma.rn.f32x2 %0, %1, %2, %3;" : "=l"(d) : "l"(a), "l"(b), "l"(c));
    return d;
}
static __device__ __forceinline__ void unpack2(unsigned long long v, float& lo, float& hi) {
    asm("mov.b64 {%0, %1}, %2;" : "=f"(lo), "=f"(hi) : "l"(v));
}
static __device__ __forceinline__ uint32_t smem_u32(const void* p) {
    uint32_t a;
    asm("{ .reg .u64 t; cvta.to.shared.u64 t, %1; cvt.u32.u64 %0, t; }" : "=r"(a) : "l"(p));
    return a;
}
// pack two f32 into bf16x2 (lo half = a, hi half = b)
static __device__ __forceinline__ uint32_t bf2(float a, float b) {
    uint32_t r;
    asm("cvt.rn.bf16x2.f32 %0, %1, %2;" : "=r"(r) : "f"(b), "f"(a));
    return r;
}

#if HAS_TC
// ---------------- tcgen05 wrappers (sm_103a pass only) ------------------------
static __device__ __forceinline__ uint64_t smem_desc(uint32_t addr) {
    const uint64_t base = (uint64_t(2) << 61) | (uint64_t(1) << 46) |
                          (uint64_t(64) << 32) | (uint64_t(1) << 16);
    return base | ((addr >> 4) & 0x3FFFu);
}
static __device__ __forceinline__ void mma_f16_ss(uint32_t d, uint64_t ad, uint64_t bd,
                                                  uint32_t idesc, uint32_t acc) {
    asm volatile(
        "{\n\t.reg .pred p;\n\tsetp.ne.u32 p, %5, 0;\n\t"
        "tcgen05.mma.cta_group::1.kind::f16 [%0], %1, %2, %3, {%4,%4,%4,%4}, p;\n\t}"
        :: "r"(d), "l"(ad), "l"(bd), "r"(idesc), "r"(0u), "r"(acc) : "memory");
}
static __device__ __forceinline__ void mma_commit(uint32_t mbar) {
    asm volatile(
        "tcgen05.commit.cta_group::1.mbarrier::arrive::one.shared::cluster.b64 [%0];"
        :: "r"(mbar) : "memory");
}
#endif
static __device__ __forceinline__ void mbar_init(uint32_t a, uint32_t cnt) {
    asm volatile("mbarrier.init.shared.b64 [%0], %1;" :: "r"(a), "r"(cnt) : "memory");
}
static __device__ __forceinline__ void mbar_wait(uint32_t mbar, uint32_t parity) {
    asm volatile(
        "{\n\t.reg .pred P1;\n\t"
        "WAIT_LOOP_%=:\n\t"
        "mbarrier.try_wait.parity.acquire.cta.shared::cta.b64 P1, [%0], %1, 0x989680;\n\t"
        "@P1 bra.uni WAIT_DONE_%=;\n\t"
        "bra.uni WAIT_LOOP_%=;\n\t"
        "WAIT_DONE_%=:\n\t}"
        :: "r"(mbar), "r"(parity) : "memory");
}

// idesc: f32 accum, bf16 A/B, N=256, M=128
#define IDESC_VAL ((1u << 4) | (1u << 7) | (1u << 10) | ((DD / 8) << 17) | ((128 / 16) << 24))

// ---------------- smem layout for k_att (tcgen05 path) ------------------------
#define SM_TMEMPTR 0
#define SM_MBAR    8
#define SM_AYS     64
#define SM_MS      576
#define SM_SSM     1088
#define SM_AXS     4096
#define SM_TILES   20480
#define OFF_AHI    0
#define OFF_ALO    16384
#define OFF_BHI    32768
#define OFF_BLO    65536
#define BUF_STRIDE 98304
#define SMEM_TOTAL (SM_TILES + 2 * BUF_STRIDE)   // 217088

// ---------------- kernel 0: init ---------------------------------------------
__global__ void k_init() {
    if (threadIdx.x < BB) g_maxAxEnc[threadIdx.x] = 0u;
}

// ---------------- kernel 1: h = feat @ W (fp32, f32x2) ------------------------
__global__ void __launch_bounds__(256, 2) k_h(const float* __restrict__ feat,
                                              const float* __restrict__ W) {
    __shared__ float fT[32 * 64];
    __shared__ float Ws[32 * 256];
    const int t  = threadIdx.x;
    const int ty = t >> 5;
    const int tx = t & 31;
    const int r0 = blockIdx.x * 64;

    unsigned long long acc[4][8];
#pragma unroll
    for (int i = 0; i < 4; i++)
#pragma unroll
        for (int j = 0; j < 8; j++) acc[i][j] = 0ull;

    for (int kt = 0; kt < 8; kt++) {
        const int k0 = kt * 32;
        {
            const int rr = t >> 2;
            const int kq = (t & 3) * 8;
            const float* fp = feat + (size_t)(r0 + rr) * DD + k0 + kq;
            float4 f0 = *(const float4*)fp;
            float4 f1 = *(const float4*)(fp + 4);
            fT[(kq + 0) * 64 + rr] = f0.x;  fT[(kq + 1) * 64 + rr] = f0.y;
            fT[(kq + 2) * 64 + rr] = f0.z;  fT[(kq + 3) * 64 + rr] = f0.w;
            fT[(kq + 4) * 64 + rr] = f1.x;  fT[(kq + 5) * 64 + rr] = f1.y;
            fT[(kq + 6) * 64 + rr] = f1.z;  fT[(kq + 7) * 64 + rr] = f1.w;
        }
        {
            const int kk = t >> 3;
            const int c0 = (t & 7) * 32;
            const float* wp = W + (size_t)(k0 + kk) * DD + c0;
#pragma unroll
            for (int u = 0; u < 8; u++)
                *(float4*)&Ws[kk * 256 + c0 + u * 4] = *(const float4*)(wp + u * 4);
        }
        __syncthreads();
#pragma unroll 4
        for (int k = 0; k < 32; k++) {
            ulonglong2 A0 = *(const ulonglong2*)&fT[k * 64 + ty * 8];
            ulonglong2 A1 = *(const ulonglong2*)&fT[k * 64 + ty * 8 + 4];
            float4 b0 = *(const float4*)&Ws[k * 256 + tx * 4];
            float4 b1 = *(const float4*)&Ws[k * 256 + 128 + tx * 4];
            unsigned long long bb[8];
            bb[0] = pack2(b0.x); bb[1] = pack2(b0.y); bb[2] = pack2(b0.z); bb[3] = pack2(b0.w);
            bb[4] = pack2(b1.x); bb[5] = pack2(b1.y); bb[6] = pack2(b1.z); bb[7] = pack2(b1.w);
            unsigned long long pp[4] = {A0.x, A0.y, A1.x, A1.y};
#pragma unroll
            for (int ii = 0; ii < 4; ii++)
#pragma unroll
                for (int dd = 0; dd < 8; dd++)
                    acc[ii][dd] = fma2(pp[ii], bb[dd], acc[ii][dd]);
        }
        __syncthreads();
    }
#pragma unroll
    for (int ii = 0; ii < 4; ii++) {
        const int re = r0 + ty * 8 + ii * 2;
        float ve[8], vo[8];
#pragma unroll
        for (int dd = 0; dd < 8; dd++) unpack2(acc[ii][dd], ve[dd], vo[dd]);
        float* pe = g_h + (size_t)re * DD;
        float* po = g_h + (size_t)(re + 1) * DD;
        *(float4*)(pe + tx * 4)       = make_float4(ve[0], ve[1], ve[2], ve[3]);
        *(float4*)(pe + 128 + tx * 4) = make_float4(ve[4], ve[5], ve[6], ve[7]);
        *(float4*)(po + tx * 4)       = make_float4(vo[0], vo[1], vo[2], vo[3]);
        *(float4*)(po + 128 + tx * 4) = make_float4(vo[4], vo[5], vo[6], vo[7]);
    }
}

// ---------------- kernel 2: Ax, Ay, maxAx ------------------------------------
__global__ void k_axy(const float* __restrict__ a1, const float* __restrict__ a2) {
    const int t   = threadIdx.x;
    const int row = blockIdx.x * 32 + (t >> 3);
    const int l8  = t & 7;
    const float* hr = g_h + (size_t)row * DD;
    float ax = 0.f, ay = 0.f;
#pragma unroll
    for (int it = 0; it < 8; it++) {
        const int c = l8 * 4 + it * 32;
        float4 h4 = *(const float4*)(hr + c);
        float4 A  = *(const float4*)(a1 + c);
        float4 Bv = *(const float4*)(a2 + c);
        ax += h4.x * A.x + h4.y * A.y + h4.z * A.z + h4.w * A.w;
        ay += h4.x * Bv.x + h4.y * Bv.y + h4.z * Bv.z + h4.w * Bv.w;
    }
#pragma unroll
    for (int off = 4; off; off >>= 1) {
        ax += __shfl_down_sync(0xffffffffu, ax, off);
        ay += __shfl_down_sync(0xffffffffu, ay, off);
    }
    if (l8 == 0) {
        g_Ax[row] = ax;
        g_Ay[row] = ay;
        atomicMax(&g_maxAxEnc[row >> 12], enc_f(ax));
    }
}

// ---------------- kernel 3: fused attention -----------------------------------
// sm_103a cubin: tcgen05 bf16 hi/lo-split MMA, fp32 accum in TMEM.
// plain sm_103 cubin: f32x2 CUDA-core fallback (two 64-row halves).
__global__ void __launch_bounds__(256, 1) k_att(const int* __restrict__ adj,
                                                float* __restrict__ out) {
    extern __shared__ char smem[];
#if HAS_TC
    const uint32_t sb = smem_u32(smem);
    const int t    = threadIdx.x;
    const int wid  = t >> 5;
    const int lane = t & 31;
    const int b    = blockIdx.y;
    const int i0   = blockIdx.x * 128;

    if (wid == 0)
        asm volatile("tcgen05.alloc.cta_group::1.sync.aligned.shared::cta.b32 [%0], %1;"
                     :: "r"(sb + SM_TMEMPTR), "r"(256) : "memory");
    if (t == 0) {
        mbar_init(sb + SM_MBAR, 1);
        mbar_init(sb + SM_MBAR + 8, 1);
    }

    // stage all Ax for this batch (16KB), Ay + M for the 128 i-rows
    float* Axs = (float*)(smem + SM_AXS);
    {
        const float4* src = (const float4*)(g_Ax + b * NN);
        float4* dst = (float4*)Axs;
        for (int q = t; q < NN / 4; q += 256) dst[q] = src[q];
    }
    float* Ays = (float*)(smem + SM_AYS);
    float* Ms  = (float*)(smem + SM_MS);
    if (t < 128) {
        float ay = g_Ay[b * NN + i0 + t];
        Ays[t] = ay;
        Ms[t]  = fmaxf(0.f, dec_f(g_maxAxEnc[b]) + ay);
    }
    __syncthreads();

    uint32_t tmem;
    asm("ld.shared.b32 %0, [%1];" : "=r"(tmem) : "r"(sb + SM_TMEMPTR));

    // P-gen mapping: thread -> (i-row i1, half of 32 j)
    const int i1   = t >> 1;
    const int half = t & 1;
    const float ay_i = Ays[i1];
    const float M_i  = Ms[i1];
    const int4* aRow = (const int4*)(adj + (size_t)b * NN * NN + (size_t)(i0 + i1) * NN);

    // B-gen mapping: thread -> (j-pair jp, 32 d at d0)
    const int jp = lane;
    const int d0 = wid * 32;
    const float* hBase = g_h + ((size_t)(b * NN) + 2 * jp) * DD + d0;

    float ssum = 0.f;

    int4 cur[8];
#pragma unroll
    for (int q = 0; q < 8; q++) cur[q] = aRow[half * 8 + q];

    for (int c = 0; c < NCHUNK; c++) {
        const int buf = c & 1;
        const int j0  = c * KC;
        const uint32_t tb = sb + SM_TILES + buf * BUF_STRIDE;
        char* tilep = smem + SM_TILES + buf * BUF_STRIDE;

        // prefetch next chunk's adj
        int4 nxt[8];
        if (c + 1 < NCHUNK) {
#pragma unroll
            for (int q = 0; q < 8; q++) nxt[q] = aRow[(c + 1) * 16 + half * 8 + q];
        }

        // wait: MMAs of chunk c-2 (same buffer) done before overwriting
        if (c >= 2) mbar_wait(sb + SM_MBAR + 8 * buf, (c / 2 - 1) & 1);

        // ---- B tiles: h^T hi/lo. row = d (128B), col = j ----
        {
            const float* r0 = hBase + (size_t)j0 * DD;
            const float* r1 = r0 + DD;
            float4 x[8], y[8];
#pragma unroll
            for (int q = 0; q < 8; q++) {
                x[q] = *(const float4*)(r0 + q * 4);
                y[q] = *(const float4*)(r1 + q * 4);
            }
#pragma unroll
            for (int q = 0; q < 8; q++) {
                const float vx[4] = {x[q].x, x[q].y, x[q].z, x[q].w};
                const float vy[4] = {y[q].x, y[q].y, y[q].z, y[q].w};
#pragma unroll
                for (int cmp = 0; cmp < 4; cmp++) {
                    const int d = d0 + q * 4 + cmp;
                    uint32_t hi = bf2(vx[cmp], vy[cmp]);
                    float fx = __uint_as_float(hi << 16);
                    float fy = __uint_as_float(hi & 0xffff0000u);
                    uint32_t lo = bf2(vx[cmp] - fx, vy[cmp] - fy);
                    uint32_t off = (uint32_t)(d * 128 + jp * 4);
                    off = off ^ ((off >> 3) & 0x70);
                    *(uint32_t*)(tilep + OFF_BHI + off) = hi;
                    *(uint32_t*)(tilep + OFF_BLO + off) = lo;
                }
            }
        }

        // ---- A tile: P hi/lo. row = i (128B), col = j ----
        {
#pragma unroll
            for (int q = 0; q < 16; q++) {
                const int jl = half * 32 + 2 * q;
                const float2 ax2 = *(const float2*)(Axs + j0 + jl);
                const int* ci = (const int*)&cur[q >> 1];
                const int a0  = ci[(q & 1) * 2];
                const int a1v = ci[(q & 1) * 2 + 1];
                float s0 = ax2.x + ay_i;
                float s1 = ax2.y + ay_i;
                float e0 = (s0 > 0.f) ? s0 : 0.2f * s0;
                float e1 = (s1 > 0.f) ? s1 : 0.2f * s1;
                float p0 = (a0 > 0)  ? __expf(e0 - M_i) : 0.f;
                float p1 = (a1v > 0) ? __expf(e1 - M_i) : 0.f;
                ssum += p0 + p1;
                uint32_t hi = bf2(p0, p1);
                float f0 = __uint_as_float(hi << 16);
                float f1 = __uint_as_float(hi & 0xffff0000u);
                uint32_t lo = bf2(p0 - f0, p1 - f1);
                uint32_t off = (uint32_t)(i1 * 128 + jl * 2);
                off = off ^ ((off >> 3) & 0x70);
                *(uint32_t*)(tilep + OFF_AHI + off) = hi;
                *(uint32_t*)(tilep + OFF_ALO + off) = lo;
            }
#pragma unroll
            for (int q = 0; q < 8; q++) cur[q] = nxt[q];
        }

        asm volatile("fence.proxy.async.shared::cta;" ::: "memory");
        __syncthreads();

        if (t == 0) {
            const uint64_t dAhi = smem_desc(tb + OFF_AHI);
            const uint64_t dAlo = smem_desc(tb + OFF_ALO);
            const uint64_t dBhi = smem_desc(tb + OFF_BHI);
            const uint64_t dBlo = smem_desc(tb + OFF_BLO);
#pragma unroll
            for (int k = 0; k < 4; k++)
                mma_f16_ss(tmem, dAhi + k * 2, dBhi + k * 2, IDESC_VAL,
                           (c == 0 && k == 0) ? 0u : 1u);
#pragma unroll
            for (int k = 0; k < 4; k++)
                mma_f16_ss(tmem, dAhi + k * 2, dBlo + k * 2, IDESC_VAL, 1u);
#pragma unroll
            for (int k = 0; k < 4; k++)
                mma_f16_ss(tmem, dAlo + k * 2, dBhi + k * 2, IDESC_VAL, 1u);
            mma_commit(sb + SM_MBAR + 8 * buf);
        }
    }

    // drain both buffers (32 commits each -> parity 1)
    mbar_wait(sb + SM_MBAR,     ((NCHUNK / 2) - 1) & 1);
    mbar_wait(sb + SM_MBAR + 8, ((NCHUNK / 2) - 1) & 1);
    asm volatile("tcgen05.fence::after_thread_sync;" ::: "memory");

    float* ssm = (float*)(smem + SM_SSM);
    ssm[t] = ssum;
    __syncthreads();

    // epilogue: warps 0-3 read TMEM (lane -> i within subpartition)
    if (wid < 4) {
        const int i = wid * 32 + lane;
        const float rs = 1.f / (ssm[2 * i] + ssm[2 * i + 1]);
        float* orow = out + (((size_t)(b * NN + i0 + i)) << 8);
#pragma unroll 1
        for (int cc = 0; cc < 8; cc++) {
            uint32_t r[32];
            asm volatile(
                "tcgen05.ld.sync.aligned.32x32b.x32.b32 "
                "{%0,%1,%2,%3,%4,%5,%6,%7,%8,%9,%10,%11,%12,%13,%14,%15,"
                "%16,%17,%18,%19,%20,%21,%22,%23,%24,%25,%26,%27,%28,%29,%30,%31}, [%32];"
                : "=r"(r[0]), "=r"(r[1]), "=r"(r[2]), "=r"(r[3]),
                  "=r"(r[4]), "=r"(r[5]), "=r"(r[6]), "=r"(r[7]),
                  "=r"(r[8]), "=r"(r[9]), "=r"(r[10]), "=r"(r[11]),
                  "=r"(r[12]), "=r"(r[13]), "=r"(r[14]), "=r"(r[15]),
                  "=r"(r[16]), "=r"(r[17]), "=r"(r[18]), "=r"(r[19]),
                  "=r"(r[20]), "=r"(r[21]), "=r"(r[22]), "=r"(r[23]),
                  "=r"(r[24]), "=r"(r[25]), "=r"(r[26]), "=r"(r[27]),
                  "=r"(r[28]), "=r"(r[29]), "=r"(r[30]), "=r"(r[31])
                : "r"(tmem + cc * 32));
            asm volatile("tcgen05.wait::ld.sync.aligned;" ::: "memory");
            float v[32];
#pragma unroll
            for (int q = 0; q < 32; q++) {
                float x = __uint_as_float(r[q]) * rs;
                v[q] = (x > 0.f) ? x : expm1f(x);
            }
#pragma unroll
            for (int q = 0; q < 8; q++)
                *(float4*)(orow + cc * 32 + q * 4) =
                    make_float4(v[q * 4], v[q * 4 + 1], v[q * 4 + 2], v[q * 4 + 3]);
        }
    }
    __syncthreads();
    if (wid == 0)
        asm volatile("tcgen05.dealloc.cta_group::1.sync.aligned.b32 %0, %1;"
                     :: "r"(tmem), "r"(256));

#else  // ---------------- fallback: f32x2 CUDA-core path ----------------------
    float* pT  = (float*)(smem);                    // 128*68 floats
    float* Axs = (float*)(smem + 34816);            // 128
    float* Ays = (float*)(smem + 35328);            // 64
    float* Ms  = (float*)(smem + 35840);            // 64
    float* ssm = (float*)(smem + 36352);            // 256

    const int t  = threadIdx.x;
    const int b  = blockIdx.y;

    for (int hh = 0; hh < 2; hh++) {
        const int i0 = blockIdx.x * 128 + hh * 64;

        if (t < 64) {
            float ay = g_Ay[b * NN + i0 + t];
            Ays[t] = ay;
            Ms[t]  = fmaxf(0.f, dec_f(g_maxAxEnc[b]) + ay);
        }
        __syncthreads();

        const int i1 = t >> 2;
        const int jc = (t & 3) * 32;
        const float ay_i = Ays[i1];
        const float M_i  = Ms[i1];
        const int ty = t >> 5;
        const int tx = t & 31;

        unsigned long long acc[4][8];
#pragma unroll
        for (int i = 0; i < 4; i++)
#pragma unroll
            for (int j = 0; j < 8; j++) acc[i][j] = 0ull;
        float ssum = 0.f;

        const int* adjrow = adj + (size_t)b * NN * NN + (size_t)(i0 + i1) * NN + jc;

        for (int jt = 0; jt < 32; jt++) {
            const int j0 = jt * 128;
            if (t < 128) Axs[t] = g_Ax[b * NN + j0 + t];
            __syncthreads();

            const int4* ar = (const int4*)(adjrow + j0);
#pragma unroll
            for (int v = 0; v < 8; v++) {
                int4 a4 = ar[v];
                const int jj = jc + v * 4;
                const int am[4] = {a4.x, a4.y, a4.z, a4.w};
#pragma unroll
                for (int u = 0; u < 4; u++) {
                    float s = Axs[jj + u] + ay_i;
                    float e = (s > 0.f) ? s : 0.2f * s;
                    float p = (am[u] > 0) ? __expf(e - M_i) : 0.f;
                    ssum += p;
                    pT[(jj + u) * 68 + i1] = p;
                }
            }
            __syncthreads();

            const float* hb = g_h + ((size_t)(b * NN + j0) << 8);
#pragma unroll 2
            for (int j = 0; j < 128; j++) {
                ulonglong2 P0 = *(const ulonglong2*)&pT[j * 68 + ty * 8];
                ulonglong2 P1 = *(const ulonglong2*)&pT[j * 68 + ty * 8 + 4];
                const float* hr = hb + ((size_t)j << 8);
                float4 h0 = *(const float4*)(hr + tx * 4);
                float4 h1 = *(const float4*)(hr + 128 + tx * 4);
                unsigned long long hhv[8];
                hhv[0] = pack2(h0.x); hhv[1] = pack2(h0.y); hhv[2] = pack2(h0.z); hhv[3] = pack2(h0.w);
                hhv[4] = pack2(h1.x); hhv[5] = pack2(h1.y); hhv[6] = pack2(h1.z); hhv[7] = pack2(h1.w);
                unsigned long long pp[4] = {P0.x, P0.y, P1.x, P1.y};
#pragma unroll
                for (int ii = 0; ii < 4; ii++)
#pragma unroll
                    for (int dd = 0; dd < 8; dd++)
                        acc[ii][dd] = fma2(pp[ii], hhv[dd], acc[ii][dd]);
            }
            __syncthreads();
        }

        ssm[i1 * 4 + (t & 3)] = ssum;
        __syncthreads();
#pragma unroll
        for (int ii = 0; ii < 4; ii++) {
            const int ie = ty * 8 + ii * 2;
            float Se = ssm[ie * 4] + ssm[ie * 4 + 1] + ssm[ie * 4 + 2] + ssm[ie * 4 + 3];
            float So = ssm[(ie + 1) * 4] + ssm[(ie + 1) * 4 + 1] +
                       ssm[(ie + 1) * 4 + 2] + ssm[(ie + 1) * 4 + 3];
            float re = 1.f / Se, ro = 1.f / So;
            float ve[8], vo[8];
#pragma unroll
            for (int dd = 0; dd < 8; dd++) {
                float lo, hi;
                unpack2(acc[ii][dd], lo, hi);
                lo *= re; hi *= ro;
                ve[dd] = (lo > 0.f) ? lo : expm1f(lo);
                vo[dd] = (hi > 0.f) ? hi : expm1f(hi);
            }
            float* pe = out + ((size_t)(b * NN + i0 + ie) << 8);
            float* po = out + ((size_t)(b * NN + i0 + ie + 1) << 8);
            *(float4*)(pe + tx * 4)       = make_float4(ve[0], ve[1], ve[2], ve[3]);
            *(float4*)(pe + 128 + tx * 4) = make_float4(ve[4], ve[5], ve[6], ve[7]);
            *(float4*)(po + tx * 4)       = make_float4(vo[0], vo[1], vo[2], vo[3]);
            *(float4*)(po + 128 + tx * 4) = make_float4(vo[4], vo[5], vo[6], vo[7]);
        }
        __syncthreads();
    }
#endif
}

// ---------------- launch ------------------------------------------------------
extern "C" void kernel_launch(void* const* d_in, const int* in_sizes, int n_in,
                              void* d_out, int out_size) {
    const float* feat = (const float*)d_in[0];
    const int*   adj  = (const int*)d_in[1];
    const float* W    = (const float*)d_in[2];
    const float* a1   = (const float*)d_in[3];
    const float* a2   = (const float*)d_in[4];
    float* out = (float*)d_out;

    static bool attr_set = false;
    if (!attr_set) {
        cudaFuncSetAttribute(k_att, cudaFuncAttributeMaxDynamicSharedMemorySize, SMEM_TOTAL);
        attr_set = true;
    }

    k_init<<<1, 32>>>();
    k_h<<<BB * NN / 64, 256>>>(feat, W);
    k_axy<<<BB * NN / 32, 256>>>(a1, a2);
    dim3 grid(NN / 128, BB);
    k_att<<<grid, 256, SMEM_TOTAL>>>(adj, out);
}

// round 5
// speedup vs baseline: 2.8185x; 1.4471x over previous
#include <cuda_runtime.h>
#include <cuda_bf16.h>
#include <cstdint>

#define BB 4
#define NN 4096
#define DD 256
#define KC 32
#define NCHUNK (NN / KC)   // 128

// tcgen05 is arch-SPECIFIC (sm_103a). The harness also runs a plain
// compute_103 pass, so every tcgen05 use must be feature-guarded.
#if defined(__CUDA_ARCH_FEAT_SM103_ALL) || \
    (defined(__CUDA_ARCH_SPECIFIC__) && (__CUDA_ARCH_SPECIFIC__ == 1030)) || \
    defined(__CUDA_ARCH_FEAT_SM100_ALL)
#define HAS_TC 1
#else
#define HAS_TC 0
#endif

// ---------------- device scratch ---------------------------------------------
__device__ float g_h[BB * NN * DD];                 // h fp32 (64 MB)
__device__ __nv_bfloat16 g_hThi[BB * DD * NN];      // h^T bf16 hi [b][d][j] (8 MB)
__device__ __nv_bfloat16 g_hTlo[BB * DD * NN];      // h^T bf16 lo (8 MB)
__device__ float g_Ax[BB * NN];
__device__ float g_Ay[BB * NN];
__device__ unsigned int g_maxAxEnc[BB];

// ---------------- helpers ----------------------------------------------------
static __device__ __forceinline__ unsigned enc_f(float f) {
    unsigned u = __float_as_uint(f);
    return (u & 0x80000000u) ? ~u : (u | 0x80000000u);
}
static __device__ __forceinline__ float dec_f(unsigned e) {
    return (e & 0x80000000u) ? __uint_as_float(e & 0x7fffffffu)
                             : __uint_as_float(~e);
}
static __device__ __forceinline__ unsigned long long pack2(float x) {
    unsigned long long r;
    asm("mov.b64 %0, {%1, %1};" : "=l"(r) : "f"(x));
    return r;
}
static __device__ __forceinline__ unsigned long long fma2(
    unsigned long long a, unsigned long long b, unsigned long long c) {
    unsigned long long d;
    asm("fma.rn.f32x2 %0, %1, %2, %3;" : "=l"(d) : "l"(a), "l"(b), "l"(c));
    return d;
}
static __device__ __forceinline__ void unpack2(unsigned long long v, float& lo, float& hi) {
    asm("mov.b64 {%0, %1}, %2;" : "=f"(lo), "=f"(hi) : "l"(v));
}
static __device__ __forceinline__ uint32_t smem_u32(const void* p) {
    uint32_t a;
    asm("{ .reg .u64 t; cvta.to.shared.u64 t, %1; cvt.u32.u64 %0, t; }" : "=r"(a) : "l"(p));
    return a;
}
// pack two f32 into bf16x2 (lo half = a, hi half = b)
static __device__ __forceinline__ uint32_t bf2(float a, float b) {
    uint32_t r;
    asm("cvt.rn.bf16x2.f32 %0, %1, %2;" : "=r"(r) : "f"(b), "f"(a));
    return r;
}
static __device__ __forceinline__ uint32_t sw128(uint32_t off) {
    return off ^ ((off >> 3) & 0x70);
}

#if HAS_TC
// ---------------- tcgen05 wrappers (sm_103a pass only) ------------------------
static __device__ __forceinline__ uint64_t smem_desc(uint32_t addr) {
    const uint64_t base = (uint64_t(2) << 61) | (uint64_t(1) << 46) |
                          (uint64_t(64) << 32) | (uint64_t(1) << 16);
    return base | ((addr >> 4) & 0x3FFFu);
}
static __device__ __forceinline__ void mma_f16_ss(uint32_t d, uint64_t ad, uint64_t bd,
                                                  uint32_t idesc, uint32_t acc) {
    asm volatile(
        "{\n\t.reg .pred p;\n\tsetp.ne.u32 p, %5, 0;\n\t"
        "tcgen05.mma.cta_group::1.kind::f16 [%0], %1, %2, %3, {%4,%4,%4,%4}, p;\n\t}"
        :: "r"(d), "l"(ad), "l"(bd), "r"(idesc), "r"(0u), "r"(acc) : "memory");
}
static __device__ __forceinline__ void mma_commit(uint32_t mbar) {
    asm volatile(
        "tcgen05.commit.cta_group::1.mbarrier::arrive::one.shared::cluster.b64 [%0];"
        :: "r"(mbar) : "memory");
}
static __device__ __forceinline__ void cpa16(uint32_t dst, const void* src) {
    asm volatile(
        "{\n\t.reg .u64 g;\n\tcvta.to.global.u64 g, %1;\n\t"
        "cp.async.cg.shared.global [%0], [g], 16;\n\t}"
        :: "r"(dst), "l"(src) : "memory");
}
#endif
static __device__ __forceinline__ void mbar_init(uint32_t a, uint32_t cnt) {
    asm volatile("mbarrier.init.shared.b64 [%0], %1;" :: "r"(a), "r"(cnt) : "memory");
}
static __device__ __forceinline__ void mbar_wait(uint32_t mbar, uint32_t parity) {
    asm volatile(
        "{\n\t.reg .pred P1;\n\t"
        "WAIT_LOOP_%=:\n\t"
        "mbarrier.try_wait.parity.acquire.cta.shared::cta.b64 P1, [%0], %1, 0x989680;\n\t"
        "@P1 bra.uni WAIT_DONE_%=;\n\t"
        "bra.uni WAIT_LOOP_%=;\n\t"
        "WAIT_DONE_%=:\n\t}"
        :: "r"(mbar), "r"(parity) : "memory");
}

// idesc: f32 accum, bf16 A/B, N=256, M=128
#define IDESC_VAL ((1u << 4) | (1u << 7) | (1u << 10) | ((DD / 8) << 17) | ((128 / 16) << 24))

// ---------------- smem layout for k_att (tcgen05 path) ------------------------
// A tile: 128 i-rows x 128B ([32 j hi | 32 j lo]) = 16KB, SW128.
// B tile: 256 d-rows x 128B ([32 j hi | 32 j lo]) = 32KB, SW128.
#define SM_TMEMPTR 0
#define SM_MBAR    8          // 2 x 8B
#define SM_AXS     1024       // 16KB (whole-batch Ax)
#define SM_SSM     17408      // 2KB (512 floats)
#define SM_AYS     19456      // 512B
#define SM_MS      19968      // 512B
#define SM_AT      20480      // 2 x 16KB
#define A_STRIDE   16384
#define SM_BT      53248      // 4 x 32KB
#define B_STRIDE   32768
#define SMEM_TOTAL 184320

// ---------------- kernel 0: init ---------------------------------------------
__global__ void k_init() {
    if (threadIdx.x < BB) g_maxAxEnc[threadIdx.x] = 0u;
}

// ---------------- kernel 1: h = feat @ W (fp32, f32x2) ------------------------
__global__ void __launch_bounds__(256, 2) k_h(const float* __restrict__ feat,
                                              const float* __restrict__ W) {
    __shared__ float fT[32 * 64];
    __shared__ float Ws[32 * 256];
    const int t  = threadIdx.x;
    const int ty = t >> 5;
    const int tx = t & 31;
    const int r0 = blockIdx.x * 64;

    unsigned long long acc[4][8];
#pragma unroll
    for (int i = 0; i < 4; i++)
#pragma unroll
        for (int j = 0; j < 8; j++) acc[i][j] = 0ull;

    for (int kt = 0; kt < 8; kt++) {
        const int k0 = kt * 32;
        {
            const int rr = t >> 2;
            const int kq = (t & 3) * 8;
            const float* fp = feat + (size_t)(r0 + rr) * DD + k0 + kq;
            float4 f0 = *(const float4*)fp;
            float4 f1 = *(const float4*)(fp + 4);
            fT[(kq + 0) * 64 + rr] = f0.x;  fT[(kq + 1) * 64 + rr] = f0.y;
            fT[(kq + 2) * 64 + rr] = f0.z;  fT[(kq + 3) * 64 + rr] = f0.w;
            fT[(kq + 4) * 64 + rr] = f1.x;  fT[(kq + 5) * 64 + rr] = f1.y;
            fT[(kq + 6) * 64 + rr] = f1.z;  fT[(kq + 7) * 64 + rr] = f1.w;
        }
        {
            const int kk = t >> 3;
            const int c0 = (t & 7) * 32;
            const float* wp = W + (size_t)(k0 + kk) * DD + c0;
#pragma unroll
            for (int u = 0; u < 8; u++)
                *(float4*)&Ws[kk * 256 + c0 + u * 4] = *(const float4*)(wp + u * 4);
        }
        __syncthreads();
#pragma unroll 4
        for (int k = 0; k < 32; k++) {
            ulonglong2 A0 = *(const ulonglong2*)&fT[k * 64 + ty * 8];
            ulonglong2 A1 = *(const ulonglong2*)&fT[k * 64 + ty * 8 + 4];
            float4 b0 = *(const float4*)&Ws[k * 256 + tx * 4];
            float4 b1 = *(const float4*)&Ws[k * 256 + 128 + tx * 4];
            unsigned long long bb[8];
            bb[0] = pack2(b0.x); bb[1] = pack2(b0.y); bb[2] = pack2(b0.z); bb[3] = pack2(b0.w);
            bb[4] = pack2(b1.x); bb[5] = pack2(b1.y); bb[6] = pack2(b1.z); bb[7] = pack2(b1.w);
            unsigned long long pp[4] = {A0.x, A0.y, A1.x, A1.y};
#pragma unroll
            for (int ii = 0; ii < 4; ii++)
#pragma unroll
                for (int dd = 0; dd < 8; dd++)
                    acc[ii][dd] = fma2(pp[ii], bb[dd], acc[ii][dd]);
        }
        __syncthreads();
    }
#pragma unroll
    for (int ii = 0; ii < 4; ii++) {
        const int re = r0 + ty * 8 + ii * 2;
        float ve[8], vo[8];
#pragma unroll
        for (int dd = 0; dd < 8; dd++) unpack2(acc[ii][dd], ve[dd], vo[dd]);
        float* pe = g_h + (size_t)re * DD;
        float* po = g_h + (size_t)(re + 1) * DD;
        *(float4*)(pe + tx * 4)       = make_float4(ve[0], ve[1], ve[2], ve[3]);
        *(float4*)(pe + 128 + tx * 4) = make_float4(ve[4], ve[5], ve[6], ve[7]);
        *(float4*)(po + tx * 4)       = make_float4(vo[0], vo[1], vo[2], vo[3]);
        *(float4*)(po + 128 + tx * 4) = make_float4(vo[4], vo[5], vo[6], vo[7]);
    }
}

// ---------------- kernel 1b: h^T in bf16 hi/lo --------------------------------
// grid (64 jt, 4 dt, 4 b), 256 threads. 64x64 transpose tiles.
__global__ void __launch_bounds__(256) k_hT() {
    __shared__ float tile[64][65];
    const int t  = threadIdx.x;
    const int jt = blockIdx.x, dt = blockIdx.y, b = blockIdx.z;

    {
        const int jr = t >> 2;
        const int dc = (t & 3) * 16;
        const float* src = g_h + ((size_t)(b * NN + jt * 64 + jr) * DD + dt * 64 + dc);
#pragma unroll
        for (int u = 0; u < 4; u++) {
            float4 v = *(const float4*)(src + u * 4);
            tile[dc + u * 4 + 0][jr] = v.x;
            tile[dc + u * 4 + 1][jr] = v.y;
            tile[dc + u * 4 + 2][jr] = v.z;
            tile[dc + u * 4 + 3][jr] = v.w;
        }
    }
    __syncthreads();
    {
        const int dl = t >> 2;
        const int jc = (t & 3) * 16;
        uint32_t hw[8], lw[8];
#pragma unroll
        for (int w = 0; w < 8; w++) {
            float f0 = tile[dl][jc + 2 * w];
            float f1 = tile[dl][jc + 2 * w + 1];
            uint32_t hi = bf2(f0, f1);
            float r0 = __uint_as_float(hi << 16);
            float r1 = __uint_as_float(hi & 0xffff0000u);
            hw[w] = hi;
            lw[w] = bf2(f0 - r0, f1 - r1);
        }
        size_t o = ((size_t)(b * DD + dt * 64 + dl) << 12) + jt * 64 + jc;
        *(uint4*)&g_hThi[o]     = make_uint4(hw[0], hw[1], hw[2], hw[3]);
        *(uint4*)&g_hThi[o + 8] = make_uint4(hw[4], hw[5], hw[6], hw[7]);
        *(uint4*)&g_hTlo[o]     = make_uint4(lw[0], lw[1], lw[2], lw[3]);
        *(uint4*)&g_hTlo[o + 8] = make_uint4(lw[4], lw[5], lw[6], lw[7]);
    }
}

// ---------------- kernel 2: Ax, Ay, maxAx ------------------------------------
__global__ void k_axy(const float* __restrict__ a1, const float* __restrict__ a2) {
    const int t   = threadIdx.x;
    const int row = blockIdx.x * 32 + (t >> 3);
    const int l8  = t & 7;
    const float* hr = g_h + (size_t)row * DD;
    float ax = 0.f, ay = 0.f;
#pragma unroll
    for (int it = 0; it < 8; it++) {
        const int c = l8 * 4 + it * 32;
        float4 h4 = *(const float4*)(hr + c);
        float4 A  = *(const float4*)(a1 + c);
        float4 Bv = *(const float4*)(a2 + c);
        ax += h4.x * A.x + h4.y * A.y + h4.z * A.z + h4.w * A.w;
        ay += h4.x * Bv.x + h4.y * Bv.y + h4.z * Bv.z + h4.w * Bv.w;
    }
#pragma unroll
    for (int off = 4; off; off >>= 1) {
        ax += __shfl_down_sync(0xffffffffu, ax, off);
        ay += __shfl_down_sync(0xffffffffu, ay, off);
    }
    if (l8 == 0) {
        g_Ax[row] = ax;
        g_Ay[row] = ay;
        atomicMax(&g_maxAxEnc[row >> 12], enc_f(ax));
    }
}

// ---------------- kernel 3: fused attention -----------------------------------
__global__ void __launch_bounds__(512, 1) k_att(const int* __restrict__ adj,
                                                float* __restrict__ out) {
    extern __shared__ char smem[];
#if HAS_TC
    const uint32_t sb = smem_u32(smem);
    const int t    = threadIdx.x;
    const int wid  = t >> 5;
    const int lane = t & 31;
    const int b    = blockIdx.y;
    const int i0   = blockIdx.x * 128;

    if (wid == 0)
        asm volatile("tcgen05.alloc.cta_group::1.sync.aligned.shared::cta.b32 [%0], %1;"
                     :: "r"(sb + SM_TMEMPTR), "r"(256) : "memory");
    if (t == 0) {
        mbar_init(sb + SM_MBAR, 1);
        mbar_init(sb + SM_MBAR + 8, 1);
    }

    // stage whole-batch Ax, plus Ay + M for the 128 i-rows
    float* Axs = (float*)(smem + SM_AXS);
    {
        const float4* src = (const float4*)(g_Ax + b * NN);
        float4* dst = (float4*)Axs;
        for (int q = t; q < NN / 4; q += 512) dst[q] = src[q];
    }
    float* Ays = (float*)(smem + SM_AYS);
    float* Ms  = (float*)(smem + SM_MS);
    if (t < 128) {
        float ay = g_Ay[b * NN + i0 + t];
        Ays[t] = ay;
        Ms[t]  = fmaxf(0.f, dec_f(g_maxAxEnc[b]) + ay);
    }

    // B prefetch mapping: thread -> (d-row bd, hi/lo select bsel)
    const int bd   = t & 255;
    const int bsel = t >> 8;
    const __nv_bfloat16* hsrc =
        (bsel ? g_hTlo : g_hThi) + ((size_t)(b * DD + bd) << 12);
    const uint32_t brow = (uint32_t)(bd * 128 + bsel * 64);

    // prologue: prefetch B(0), B(1)
#pragma unroll
    for (int p = 0; p < 2; p++) {
        const __nv_bfloat16* src = hsrc + p * KC;
#pragma unroll
        for (int s = 0; s < 4; s++)
            cpa16(sb + SM_BT + p * B_STRIDE + sw128(brow + s * 16), src + s * 8);
        asm volatile("cp.async.commit_group;" ::: "memory");
    }

    __syncthreads();

    uint32_t tmem;
    asm("ld.shared.b32 %0, [%1];" : "=r"(tmem) : "r"(sb + SM_TMEMPTR));

    // A-gen mapping: thread -> (i-row i1, 8-j quarter q)
    const int i1 = t >> 2;
    const int q  = t & 3;
    const float ay_i = Ays[i1];
    const float M_i  = Ms[i1];
    const int4* aRow = (const int4*)(adj + (size_t)b * NN * NN + (size_t)(i0 + i1) * NN);

    float ssum = 0.f;

    // adj regs for chunk 0
    int4 cur0 = aRow[q * 2], cur1 = aRow[q * 2 + 1];

    for (int c = 0; c < NCHUNK; c++) {
        const int abuf = c & 1;
        const int bbuf = c & 3;

        // free buffers of chunk c-2 (A[abuf], B[(c-2)&3] = target of prefetch below)
        if (c >= 2) mbar_wait(sb + SM_MBAR + 8 * abuf, (c / 2 - 1) & 1);

        // prefetch B(c+2) into ring slot (c+2)&3; always commit (maybe empty group)
        if (c + 2 < NCHUNK) {
            const __nv_bfloat16* src = hsrc + (c + 2) * KC;
            const uint32_t base = sb + SM_BT + ((c + 2) & 3) * B_STRIDE;
#pragma unroll
            for (int s = 0; s < 4; s++)
                cpa16(base + sw128(brow + s * 16), src + s * 8);
        }
        asm volatile("cp.async.commit_group;" ::: "memory");

        // adj regs for chunk c+1
        int4 n0, n1;
        if (c + 1 < NCHUNK) {
            n0 = aRow[(c + 1) * 8 + q * 2];
            n1 = aRow[(c + 1) * 8 + q * 2 + 1];
        }

        // ---- build A tile (P hi/lo) ----
        {
            const float4 axa = *(const float4*)&Axs[c * KC + q * 8];
            const float4 axb = *(const float4*)&Axs[c * KC + q * 8 + 4];
            const float axv[8] = {axa.x, axa.y, axa.z, axa.w, axb.x, axb.y, axb.z, axb.w};
            const int   am[8]  = {cur0.x, cur0.y, cur0.z, cur0.w, cur1.x, cur1.y, cur1.z, cur1.w};
            float pv[8];
#pragma unroll
            for (int v = 0; v < 8; v++) {
                float s = axv[v] + ay_i;
                float e = (s > 0.f) ? s : 0.2f * s;
                float p = (am[v] > 0) ? __expf(e - M_i) : 0.f;
                ssum += p;
                pv[v] = p;
            }
            uint32_t hw[4], lw[4];
#pragma unroll
            for (int w = 0; w < 4; w++) {
                uint32_t hi = bf2(pv[2 * w], pv[2 * w + 1]);
                float r0 = __uint_as_float(hi << 16);
                float r1 = __uint_as_float(hi & 0xffff0000u);
                hw[w] = hi;
                lw[w] = bf2(pv[2 * w] - r0, pv[2 * w + 1] - r1);
            }
            char* ab = smem + SM_AT + abuf * A_STRIDE;
            const uint32_t off = (uint32_t)(i1 * 128 + q * 16);
            *(uint4*)(ab + sw128(off))      = make_uint4(hw[0], hw[1], hw[2], hw[3]);
            *(uint4*)(ab + sw128(off + 64)) = make_uint4(lw[0], lw[1], lw[2], lw[3]);
        }
        cur0 = n0; cur1 = n1;

        // B(c) must have landed (2 groups younger may still fly)
        asm volatile("cp.async.wait_group 2;" ::: "memory");
        asm volatile("fence.proxy.async.shared::cta;" ::: "memory");
        __syncthreads();

        if (t == 0) {
            const uint64_t dA = smem_desc(sb + SM_AT + abuf * A_STRIDE);
            const uint64_t dB = smem_desc(sb + SM_BT + bbuf * B_STRIDE);
            // hi*hi (k=0,1), hi*lo, lo*hi. lo halves at +64B = desc+4.
            mma_f16_ss(tmem, dA,     dB,     IDESC_VAL, c > 0 ? 1u : 0u);
            mma_f16_ss(tmem, dA + 2, dB + 2, IDESC_VAL, 1u);
            mma_f16_ss(tmem, dA,     dB + 4, IDESC_VAL, 1u);
            mma_f16_ss(tmem, dA + 2, dB + 6, IDESC_VAL, 1u);
            mma_f16_ss(tmem, dA + 4, dB,     IDESC_VAL, 1u);
            mma_f16_ss(tmem, dA + 6, dB + 2, IDESC_VAL, 1u);
            mma_commit(sb + SM_MBAR + 8 * abuf);
        }
    }

    // drain
    mbar_wait(sb + SM_MBAR,     ((NCHUNK / 2) - 1) & 1);
    mbar_wait(sb + SM_MBAR + 8, ((NCHUNK / 2) - 1) & 1);
    asm volatile("tcgen05.fence::after_thread_sync;" ::: "memory");

    float* ssm = (float*)(smem + SM_SSM);
    ssm[t] = ssum;
    __syncthreads();

    // epilogue: warps 0-3 read TMEM (lane -> i within subpartition)
    if (t < 128) {
        const int i = t;
        const float rs = 1.f / (ssm[4 * i] + ssm[4 * i + 1] + ssm[4 * i + 2] + ssm[4 * i + 3]);
        float* orow = out + (((size_t)(b * NN + i0 + i)) << 8);
#pragma unroll 1
        for (int cc = 0; cc < 8; cc++) {
            uint32_t r[32];
            asm volatile(
                "tcgen05.ld.sync.aligned.32x32b.x32.b32 "
                "{%0,%1,%2,%3,%4,%5,%6,%7,%8,%9,%10,%11,%12,%13,%14,%15,"
                "%16,%17,%18,%19,%20,%21,%22,%23,%24,%25,%26,%27,%28,%29,%30,%31}, [%32];"
                : "=r"(r[0]), "=r"(r[1]), "=r"(r[2]), "=r"(r[3]),
                  "=r"(r[4]), "=r"(r[5]), "=r"(r[6]), "=r"(r[7]),
                  "=r"(r[8]), "=r"(r[9]), "=r"(r[10]), "=r"(r[11]),
                  "=r"(r[12]), "=r"(r[13]), "=r"(r[14]), "=r"(r[15]),
                  "=r"(r[16]), "=r"(r[17]), "=r"(r[18]), "=r"(r[19]),
                  "=r"(r[20]), "=r"(r[21]), "=r"(r[22]), "=r"(r[23]),
                  "=r"(r[24]), "=r"(r[25]), "=r"(r[26]), "=r"(r[27]),
                  "=r"(r[28]), "=r"(r[29]), "=r"(r[30]), "=r"(r[31])
                : "r"(tmem + cc * 32));
            asm volatile("tcgen05.wait::ld.sync.aligned;" ::: "memory");
            float v[32];
#pragma unroll
            for (int qq = 0; qq < 32; qq++) {
                float x = __uint_as_float(r[qq]) * rs;
                v[qq] = (x > 0.f) ? x : expm1f(x);
            }
#pragma unroll
            for (int qq = 0; qq < 8; qq++)
                *(float4*)(orow + cc * 32 + qq * 4) =
                    make_float4(v[qq * 4], v[qq * 4 + 1], v[qq * 4 + 2], v[qq * 4 + 3]);
        }
    }
    __syncthreads();
    if (wid == 0)
        asm volatile("tcgen05.dealloc.cta_group::1.sync.aligned.b32 %0, %1;"
                     :: "r"(tmem), "r"(256));

#else  // ---------------- fallback: f32x2 CUDA-core path (512 threads) --------
    float* pT  = (float*)(smem);                    // 128 j x 132 (i+pad)
    float* Axs = (float*)(smem + 67584);            // 128
    float* Ays = (float*)(smem + 68096);            // 128
    float* Ms  = (float*)(smem + 68608);            // 128
    float* ssm = (float*)(smem + 69120);            // 512

    const int t  = threadIdx.x;
    const int b  = blockIdx.y;
    const int i0 = blockIdx.x * 128;

    if (t < 128) {
        float ay = g_Ay[b * NN + i0 + t];
        Ays[t] = ay;
        Ms[t]  = fmaxf(0.f, dec_f(g_maxAxEnc[b]) + ay);
    }
    __syncthreads();

    const int i1 = t >> 2;
    const int jc = (t & 3) * 32;
    const float ay_i = Ays[i1];
    const float M_i  = Ms[i1];
    const int ty = t >> 5;
    const int tx = t & 31;

    unsigned long long acc[4][8];
#pragma unroll
    for (int i = 0; i < 4; i++)
#pragma unroll
        for (int j = 0; j < 8; j++) acc[i][j] = 0ull;
    float ssum = 0.f;

    const int* adjrow = adj + (size_t)b * NN * NN + (size_t)(i0 + i1) * NN + jc;

    for (int jt = 0; jt < 32; jt++) {
        const int j0 = jt * 128;
        if (t < 128) Axs[t] = g_Ax[b * NN + j0 + t];
        __syncthreads();

        const int4* ar = (const int4*)(adjrow + j0);
#pragma unroll
        for (int v = 0; v < 8; v++) {
            int4 a4 = ar[v];
            const int jj = jc + v * 4;
            const int am[4] = {a4.x, a4.y, a4.z, a4.w};
#pragma unroll
            for (int u = 0; u < 4; u++) {
                float s = Axs[jj + u] + ay_i;
                float e = (s > 0.f) ? s : 0.2f * s;
                float p = (am[u] > 0) ? __expf(e - M_i) : 0.f;
                ssum += p;
                pT[(jj + u) * 132 + i1] = p;
            }
        }
        __syncthreads();

        const float* hb = g_h + ((size_t)(b * NN + j0) << 8);
#pragma unroll 2
        for (int j = 0; j < 128; j++) {
            ulonglong2 P0 = *(const ulonglong2*)&pT[j * 132 + ty * 8];
            ulonglong2 P1 = *(const ulonglong2*)&pT[j * 132 + ty * 8 + 4];
            const float* hr = hb + ((size_t)j << 8);
            float4 h0 = *(const float4*)(hr + tx * 4);
            float4 h1 = *(const float4*)(hr + 128 + tx * 4);
            unsigned long long hhv[8];
            hhv[0] = pack2(h0.x); hhv[1] = pack2(h0.y); hhv[2] = pack2(h0.z); hhv[3] = pack2(h0.w);
            hhv[4] = pack2(h1.x); hhv[5] = pack2(h1.y); hhv[6] = pack2(h1.z); hhv[7] = pack2(h1.w);
            unsigned long long pp[4] = {P0.x, P0.y, P1.x, P1.y};
#pragma unroll
            for (int ii = 0; ii < 4; ii++)
#pragma unroll
                for (int dd = 0; dd < 8; dd++)
                    acc[ii][dd] = fma2(pp[ii], hhv[dd], acc[ii][dd]);
        }
        __syncthreads();
    }

    ssm[t] = ssum;
    __syncthreads();
#pragma unroll
    for (int ii = 0; ii < 4; ii++) {
        const int ie = ty * 8 + ii * 2;
        float Se = ssm[ie * 4] + ssm[ie * 4 + 1] + ssm[ie * 4 + 2] + ssm[ie * 4 + 3];
        float So = ssm[(ie + 1) * 4] + ssm[(ie + 1) * 4 + 1] +
                   ssm[(ie + 1) * 4 + 2] + ssm[(ie + 1) * 4 + 3];
        float re = 1.f / Se, ro = 1.f / So;
        float ve[8], vo[8];
#pragma unroll
        for (int dd = 0; dd < 8; dd++) {
            float lo, hi;
            unpack2(acc[ii][dd], lo, hi);
            lo *= re; hi *= ro;
            ve[dd] = (lo > 0.f) ? lo : expm1f(lo);
            vo[dd] = (hi > 0.f) ? hi : expm1f(hi);
        }
        float* pe = out + ((size_t)(b * NN + i0 + ie) << 8);
        float* po = out + ((size_t)(b * NN + i0 + ie + 1) << 8);
        *(float4*)(pe + tx * 4)       = make_float4(ve[0], ve[1], ve[2], ve[3]);
        *(float4*)(pe + 128 + tx * 4) = make_float4(ve[4], ve[5], ve[6], ve[7]);
        *(float4*)(po + tx * 4)       = make_float4(vo[0], vo[1], vo[2], vo[3]);
        *(float4*)(po + 128 + tx * 4) = make_float4(vo[4], vo[5], vo[6], vo[7]);
    }
#endif
}

// ---------------- launch ------------------------------------------------------
extern "C" void kernel_launch(void* const* d_in, const int* in_sizes, int n_in,
                              void* d_out, int out_size) {
    const float* feat = (const float*)d_in[0];
    const int*   adj  = (const int*)d_in[1];
    const float* W    = (const float*)d_in[2];
    const float* a1   = (const float*)d_in[3];
    const float* a2   = (const float*)d_in[4];
    float* out = (float*)d_out;

    static bool attr_set = false;
    if (!attr_set) {
        cudaFuncSetAttribute(k_att, cudaFuncAttributeMaxDynamicSharedMemorySize, SMEM_TOTAL);
        attr_set = true;
    }

    k_init<<<1, 32>>>();
    k_h<<<BB * NN / 64, 256>>>(feat, W);
    k_axy<<<BB * NN / 32, 256>>>(a1, a2);
    dim3 gT(64, 4, 4);
    k_hT<<<gT, 256>>>();
    dim3 grid(NN / 128, BB);
    k_att<<<grid, 512, SMEM_TOTAL>>>(adj, out);
}

// round 6
// speedup vs baseline: 4.4587x; 1.5819x over previous
#include <cuda_runtime.h>
#include <cuda_bf16.h>
#include <cstdint>

#define BB 4
#define NN 4096
#define DD 256
#define KC 32
#define NCHUNK (NN / KC)   // 128
#define NCHH   (DD / KC)   // 8 k-chunks for k_h

// tcgen05 is arch-SPECIFIC (sm_103a). The harness also runs a plain
// compute_103 pass, so every tcgen05 use must be feature-guarded.
#if defined(__CUDA_ARCH_FEAT_SM103_ALL) || \
    (defined(__CUDA_ARCH_SPECIFIC__) && (__CUDA_ARCH_SPECIFIC__ == 1030)) || \
    defined(__CUDA_ARCH_FEAT_SM100_ALL)
#define HAS_TC 1
#else
#define HAS_TC 0
#endif

// ---------------- device scratch ---------------------------------------------
__device__ float g_h[BB * NN * DD];                 // h fp32 (64 MB)
__device__ __nv_bfloat16 g_hThi[BB * DD * NN];      // h^T bf16 hi [b][d][j]
__device__ __nv_bfloat16 g_hTlo[BB * DD * NN];      // h^T bf16 lo
__device__ __nv_bfloat16 g_WThi[DD * DD];           // W^T bf16 hi [c][k]
__device__ __nv_bfloat16 g_WTlo[DD * DD];           // W^T bf16 lo
__device__ float g_Ax[BB * NN];
__device__ float g_Ay[BB * NN];
__device__ unsigned int g_maxAxEnc[BB];

// ---------------- helpers ----------------------------------------------------
static __device__ __forceinline__ unsigned enc_f(float f) {
    unsigned u = __float_as_uint(f);
    return (u & 0x80000000u) ? ~u : (u | 0x80000000u);
}
static __device__ __forceinline__ float dec_f(unsigned e) {
    return (e & 0x80000000u) ? __uint_as_float(e & 0x7fffffffu)
                             : __uint_as_float(~e);
}
static __device__ __forceinline__ uint32_t smem_u32(const void* p) {
    uint32_t a;
    asm("{ .reg .u64 t; cvta.to.shared.u64 t, %1; cvt.u32.u64 %0, t; }" : "=r"(a) : "l"(p));
    return a;
}
// pack two f32 into bf16x2 (a -> low half, b -> high half)
static __device__ __forceinline__ uint32_t bf2(float a, float b) {
    uint32_t r;
    asm("cvt.rn.bf16x2.f32 %0, %1, %2;" : "=r"(r) : "f"(b), "f"(a));
    return r;
}
static __device__ __forceinline__ uint32_t sw128(uint32_t off) {
    return off ^ ((off >> 3) & 0x70);
}

#if HAS_TC
// ---------------- tcgen05 wrappers (sm_103a pass only) ------------------------
static __device__ __forceinline__ uint64_t smem_desc(uint32_t addr) {
    const uint64_t base = (uint64_t(2) << 61) | (uint64_t(1) << 46) |
                          (uint64_t(64) << 32) | (uint64_t(1) << 16);
    return base | ((addr >> 4) & 0x3FFFu);
}
static __device__ __forceinline__ void mma_f16_ss(uint32_t d, uint64_t ad, uint64_t bd,
                                                  uint32_t idesc, uint32_t acc) {
    asm volatile(
        "{\n\t.reg .pred p;\n\tsetp.ne.u32 p, %5, 0;\n\t"
        "tcgen05.mma.cta_group::1.kind::f16 [%0], %1, %2, %3, {%4,%4,%4,%4}, p;\n\t}"
        :: "r"(d), "l"(ad), "l"(bd), "r"(idesc), "r"(0u), "r"(acc) : "memory");
}
static __device__ __forceinline__ void mma_commit(uint32_t mbar) {
    asm volatile(
        "tcgen05.commit.cta_group::1.mbarrier::arrive::one.shared::cluster.b64 [%0];"
        :: "r"(mbar) : "memory");
}
static __device__ __forceinline__ void cpa16(uint32_t dst, const void* src) {
    asm volatile(
        "{\n\t.reg .u64 g;\n\tcvta.to.global.u64 g, %1;\n\t"
        "cp.async.cg.shared.global [%0], [g], 16;\n\t}"
        :: "r"(dst), "l"(src) : "memory");
}
#endif
static __device__ __forceinline__ void mbar_init(uint32_t a, uint32_t cnt) {
    asm volatile("mbarrier.init.shared.b64 [%0], %1;" :: "r"(a), "r"(cnt) : "memory");
}
static __device__ __forceinline__ void mbar_wait(uint32_t mbar, uint32_t parity) {
    asm volatile(
        "{\n\t.reg .pred P1;\n\t"
        "WAIT_LOOP_%=:\n\t"
        "mbarrier.try_wait.parity.acquire.cta.shared::cta.b64 P1, [%0], %1, 0x989680;\n\t"
        "@P1 bra.uni WAIT_DONE_%=;\n\t"
        "bra.uni WAIT_LOOP_%=;\n\t"
        "WAIT_DONE_%=:\n\t}"
        :: "r"(mbar), "r"(parity) : "memory");
}

// idesc: f32 accum, bf16 A/B, N=256, M=128
#define IDESC_VAL ((1u << 4) | (1u << 7) | (1u << 10) | ((DD / 8) << 17) | ((128 / 16) << 24))

// ---------------- smem layout: k_att ------------------------------------------
#define SM_TMEMPTR 0
#define SM_MBAR    8          // 3 x 8B
#define SM_SSM     1024       // 512 floats
#define SM_AYS     3072       // 128 floats
#define SM_MS      3584       // 128 floats
#define SM_AT      4096       // 3 x 16KB
#define A_STRIDE   16384
#define SM_BT      53248      // 5 x 32KB
#define B_STRIDE   32768
#define SMEM_TOTAL 217088

// ---------------- smem layout: k_h_tc -----------------------------------------
#define HM_TMEMPTR 0
#define HM_MBAR    8          // 2 x 8B
#define HM_A1      1024       // 256 floats
#define HM_A2      2048       // 256 floats
#define HM_RED     3072       // 128 uints
#define HM_AT      4096       // 2 x 16KB
#define HM_BT      36864      // 4 x 32KB
#define SMEM_H_TOTAL 167936

// ---------------- kernel: W^T split + init ------------------------------------
__global__ void __launch_bounds__(256) k_WT(const float* __restrict__ W) {
    __shared__ float tile[64][65];
    const int t  = threadIdx.x;
    const int kt = blockIdx.x, ct = blockIdx.y;
    if (kt == 0 && ct == 0 && t < BB) g_maxAxEnc[t] = 0u;

    {
        const int kr = t >> 2;
        const int cq = (t & 3) * 16;
        const float* src = W + (size_t)(kt * 64 + kr) * DD + ct * 64 + cq;
#pragma unroll
        for (int u = 0; u < 4; u++) {
            float4 v = *(const float4*)(src + u * 4);
            tile[cq + u * 4 + 0][kr] = v.x;
            tile[cq + u * 4 + 1][kr] = v.y;
            tile[cq + u * 4 + 2][kr] = v.z;
            tile[cq + u * 4 + 3][kr] = v.w;
        }
    }
    __syncthreads();
    {
        const int cl = t >> 2;
        const int kq = (t & 3) * 16;
        uint32_t hw[8], lw[8];
#pragma unroll
        for (int w = 0; w < 8; w++) {
            float f0 = tile[cl][kq + 2 * w];
            float f1 = tile[cl][kq + 2 * w + 1];
            uint32_t hi = bf2(f0, f1);
            float r0 = __uint_as_float(hi << 16);
            float r1 = __uint_as_float(hi & 0xffff0000u);
            hw[w] = hi;
            lw[w] = bf2(f0 - r0, f1 - r1);
        }
        size_t o = (size_t)(ct * 64 + cl) * DD + kt * 64 + kq;
        *(uint4*)&g_WThi[o]     = make_uint4(hw[0], hw[1], hw[2], hw[3]);
        *(uint4*)&g_WThi[o + 8] = make_uint4(hw[4], hw[5], hw[6], hw[7]);
        *(uint4*)&g_WTlo[o]     = make_uint4(lw[0], lw[1], lw[2], lw[3]);
        *(uint4*)&g_WTlo[o + 8] = make_uint4(lw[4], lw[5], lw[6], lw[7]);
    }
}

// ---------------- kernel: h = feat @ W via tcgen05 + fused Ax/Ay/maxAx --------
__global__ void __launch_bounds__(512, 1) k_h_tc(const float* __restrict__ feat,
                                                 const float* __restrict__ W,
                                                 const float* __restrict__ a1,
                                                 const float* __restrict__ a2) {
    extern __shared__ char smem[];
    const int t  = threadIdx.x;
    const int r0 = blockIdx.x * 128;
#if HAS_TC
    const uint32_t sb = smem_u32(smem);
    const int wid = t >> 5;

    if (wid == 0)
        asm volatile("tcgen05.alloc.cta_group::1.sync.aligned.shared::cta.b32 [%0], %1;"
                     :: "r"(sb + HM_TMEMPTR), "r"(256) : "memory");
    if (t == 0) {
        mbar_init(sb + HM_MBAR, 1);
        mbar_init(sb + HM_MBAR + 8, 1);
    }
    float* a1s = (float*)(smem + HM_A1);
    float* a2s = (float*)(smem + HM_A2);
    if (t < 256) a1s[t] = a1[t];
    else         a2s[t - 256] = a2[t - 256];

    // B (W^T) cp.async mapping: thread -> (split s, row r); 64B per chunk
    const int bs = t >> 8;
    const int br = t & 255;
    const __nv_bfloat16* wsrc = (bs ? g_WTlo : g_WThi) + (size_t)br * DD;
    uint32_t boff[4];
#pragma unroll
    for (int u = 0; u < 4; u++) boff[u] = sw128((uint32_t)(br * 128 + bs * 64 + u * 16));

    // A (feat) convert mapping: thread -> (row m, 8-k quarter q)
    const int m = t >> 2;
    const int q = t & 3;
    const float* fsrc = feat + (size_t)(r0 + m) * DD + q * 8;
    const uint32_t ahoff = sw128((uint32_t)(m * 128 + q * 16));
    const uint32_t aloff = sw128((uint32_t)(m * 128 + 64 + q * 16));

    // prologue: prefetch B(0), B(1); load feat chunk 0
#pragma unroll
    for (int p = 0; p < 2; p++) {
        const __nv_bfloat16* src = wsrc + p * KC;
        const uint32_t base = sb + HM_BT + p * B_STRIDE;
#pragma unroll
        for (int u = 0; u < 4; u++) cpa16(base + boff[u], src + u * 8);
        asm volatile("cp.async.commit_group;" ::: "memory");
    }
    float4 fc0 = *(const float4*)fsrc;
    float4 fc1 = *(const float4*)(fsrc + 4);

    __syncthreads();
    uint32_t tmem;
    asm("ld.shared.b32 %0, [%1];" : "=r"(tmem) : "r"(sb + HM_TMEMPTR));

    for (int c = 0; c < NCHH; c++) {
        const int abuf = c & 1;

        if (c >= 2) mbar_wait(sb + HM_MBAR + 8 * abuf, (c / 2 - 1) & 1);

        if (c + 2 < NCHH) {
            const __nv_bfloat16* src = wsrc + (c + 2) * KC;
            const uint32_t base = sb + HM_BT + ((c + 2) & 3) * B_STRIDE;
#pragma unroll
            for (int u = 0; u < 4; u++) cpa16(base + boff[u], src + u * 8);
        }
        asm volatile("cp.async.commit_group;" ::: "memory");

        float4 fn0, fn1;
        if (c + 1 < NCHH) {
            fn0 = *(const float4*)(fsrc + (c + 1) * KC);
            fn1 = *(const float4*)(fsrc + (c + 1) * KC + 4);
        }

        // convert + store A tile
        {
            const float fv[8] = {fc0.x, fc0.y, fc0.z, fc0.w, fc1.x, fc1.y, fc1.z, fc1.w};
            uint32_t hw[4], lw[4];
#pragma unroll
            for (int w = 0; w < 4; w++) {
                uint32_t hi = bf2(fv[2 * w], fv[2 * w + 1]);
                float rr0 = __uint_as_float(hi << 16);
                float rr1 = __uint_as_float(hi & 0xffff0000u);
                hw[w] = hi;
                lw[w] = bf2(fv[2 * w] - rr0, fv[2 * w + 1] - rr1);
            }
            char* ab = smem + HM_AT + abuf * A_STRIDE;
            *(uint4*)(ab + ahoff) = make_uint4(hw[0], hw[1], hw[2], hw[3]);
            *(uint4*)(ab + aloff) = make_uint4(lw[0], lw[1], lw[2], lw[3]);
        }
        fc0 = fn0; fc1 = fn1;

        asm volatile("cp.async.wait_group 2;" ::: "memory");
        asm volatile("fence.proxy.async.shared::cta;" ::: "memory");
        __syncthreads();

        if (t == 0) {
            const uint64_t dA = smem_desc(sb + HM_AT + abuf * A_STRIDE);
            const uint64_t dB = smem_desc(sb + HM_BT + (c & 3) * B_STRIDE);
            mma_f16_ss(tmem, dA,     dB,     IDESC_VAL, c > 0 ? 1u : 0u);
            mma_f16_ss(tmem, dA + 2, dB + 2, IDESC_VAL, 1u);
            mma_f16_ss(tmem, dA,     dB + 4, IDESC_VAL, 1u);
            mma_f16_ss(tmem, dA + 2, dB + 6, IDESC_VAL, 1u);
            mma_f16_ss(tmem, dA + 4, dB,     IDESC_VAL, 1u);
            mma_f16_ss(tmem, dA + 6, dB + 2, IDESC_VAL, 1u);
            mma_commit(sb + HM_MBAR + 8 * abuf);
        }
    }

    mbar_wait(sb + HM_MBAR,     ((NCHH / 2) - 1) & 1);
    mbar_wait(sb + HM_MBAR + 8, ((NCHH / 2) - 1) & 1);
    asm volatile("tcgen05.fence::after_thread_sync;" ::: "memory");

    unsigned* RED = (unsigned*)(smem + HM_RED);
    if (t < 128) {
        const int grow = r0 + t;
        float ax = 0.f, ay = 0.f;
        float* hrow = g_h + (size_t)grow * DD;
#pragma unroll 1
        for (int cc = 0; cc < 8; cc++) {
            uint32_t r[32];
            asm volatile(
                "tcgen05.ld.sync.aligned.32x32b.x32.b32 "
                "{%0,%1,%2,%3,%4,%5,%6,%7,%8,%9,%10,%11,%12,%13,%14,%15,"
                "%16,%17,%18,%19,%20,%21,%22,%23,%24,%25,%26,%27,%28,%29,%30,%31}, [%32];"
                : "=r"(r[0]), "=r"(r[1]), "=r"(r[2]), "=r"(r[3]),
                  "=r"(r[4]), "=r"(r[5]), "=r"(r[6]), "=r"(r[7]),
                  "=r"(r[8]), "=r"(r[9]), "=r"(r[10]), "=r"(r[11]),
                  "=r"(r[12]), "=r"(r[13]), "=r"(r[14]), "=r"(r[15]),
                  "=r"(r[16]), "=r"(r[17]), "=r"(r[18]), "=r"(r[19]),
                  "=r"(r[20]), "=r"(r[21]), "=r"(r[22]), "=r"(r[23]),
                  "=r"(r[24]), "=r"(r[25]), "=r"(r[26]), "=r"(r[27]),
                  "=r"(r[28]), "=r"(r[29]), "=r"(r[30]), "=r"(r[31])
                : "r"(tmem + cc * 32));
            asm volatile("tcgen05.wait::ld.sync.aligned;" ::: "memory");
            float v[32];
#pragma unroll
            for (int k = 0; k < 32; k++) {
                v[k] = __uint_as_float(r[k]);
                ax += v[k] * a1s[cc * 32 + k];
                ay += v[k] * a2s[cc * 32 + k];
            }
#pragma unroll
            for (int k = 0; k < 8; k++)
                *(float4*)(hrow + cc * 32 + k * 4) =
                    make_float4(v[k * 4], v[k * 4 + 1], v[k * 4 + 2], v[k * 4 + 3]);
        }
        g_Ax[grow] = ax;
        g_Ay[grow] = ay;
        RED[t] = enc_f(ax);
    }
    __syncthreads();
    if (t < 32) {
        unsigned mx = RED[t];
        mx = max(mx, RED[t + 32]);
        mx = max(mx, RED[t + 64]);
        mx = max(mx, RED[t + 96]);
#pragma unroll
        for (int off = 16; off; off >>= 1)
            mx = max(mx, __shfl_down_sync(0xffffffffu, mx, off));
        if (t == 0) atomicMax(&g_maxAxEnc[r0 >> 12], mx);
    }
    __syncthreads();
    if (wid == 0)
        asm volatile("tcgen05.dealloc.cta_group::1.sync.aligned.b32 %0, %1;"
                     :: "r"(tmem), "r"(256));
#else
    // correctness-only fallback (never selected on GB300)
    const int m  = t >> 2;
    const int cq = (t & 3) * 64;
    const int grow = r0 + m;
    const float* fr = feat + (size_t)grow * DD;
    for (int j = 0; j < 64; j++) {
        float acc = 0.f;
        for (int k = 0; k < DD; k++) acc += fr[k] * W[(size_t)k * DD + cq + j];
        g_h[(size_t)grow * DD + cq + j] = acc;
    }
    __syncthreads();
    unsigned* RED = (unsigned*)(smem + HM_RED);
    if (t < 128) {
        const int gr = r0 + t;
        const float* hr = g_h + (size_t)gr * DD;
        float ax = 0.f, ay = 0.f;
        for (int k = 0; k < DD; k++) { ax += hr[k] * a1[k]; ay += hr[k] * a2[k]; }
        g_Ax[gr] = ax;
        g_Ay[gr] = ay;
        RED[t] = enc_f(ax);
    }
    __syncthreads();
    if (t < 32) {
        unsigned mx = RED[t];
        mx = max(mx, RED[t + 32]);
        mx = max(mx, RED[t + 64]);
        mx = max(mx, RED[t + 96]);
#pragma unroll
        for (int off = 16; off; off >>= 1)
            mx = max(mx, __shfl_down_sync(0xffffffffu, mx, off));
        if (t == 0) atomicMax(&g_maxAxEnc[r0 >> 12], mx);
    }
#endif
}

// ---------------- kernel: h^T in bf16 hi/lo -----------------------------------
__global__ void __launch_bounds__(256) k_hT() {
    __shared__ float tile[64][65];
    const int t  = threadIdx.x;
    const int jt = blockIdx.x, dt = blockIdx.y, b = blockIdx.z;
    {
        const int jr = t >> 2;
        const int dc = (t & 3) * 16;
        const float* src = g_h + ((size_t)(b * NN + jt * 64 + jr) * DD + dt * 64 + dc);
#pragma unroll
        for (int u = 0; u < 4; u++) {
            float4 v = *(const float4*)(src + u * 4);
            tile[dc + u * 4 + 0][jr] = v.x;
            tile[dc + u * 4 + 1][jr] = v.y;
            tile[dc + u * 4 + 2][jr] = v.z;
            tile[dc + u * 4 + 3][jr] = v.w;
        }
    }
    __syncthreads();
    {
        const int dl = t >> 2;
        const int jc = (t & 3) * 16;
        uint32_t hw[8], lw[8];
#pragma unroll
        for (int w = 0; w < 8; w++) {
            float f0 = tile[dl][jc + 2 * w];
            float f1 = tile[dl][jc + 2 * w + 1];
            uint32_t hi = bf2(f0, f1);
            float r0 = __uint_as_float(hi << 16);
            float r1 = __uint_as_float(hi & 0xffff0000u);
            hw[w] = hi;
            lw[w] = bf2(f0 - r0, f1 - r1);
        }
        size_t o = ((size_t)(b * DD + dt * 64 + dl) << 12) + jt * 64 + jc;
        *(uint4*)&g_hThi[o]     = make_uint4(hw[0], hw[1], hw[2], hw[3]);
        *(uint4*)&g_hThi[o + 8] = make_uint4(hw[4], hw[5], hw[6], hw[7]);
        *(uint4*)&g_hTlo[o]     = make_uint4(lw[0], lw[1], lw[2], lw[3]);
        *(uint4*)&g_hTlo[o + 8] = make_uint4(lw[4], lw[5], lw[6], lw[7]);
    }
}

// ---------------- kernel: fused attention -------------------------------------
__global__ void __launch_bounds__(512, 1) k_att(const int* __restrict__ adj,
                                                float* __restrict__ out) {
    extern __shared__ char smem[];
#if HAS_TC
    const uint32_t sb = smem_u32(smem);
    const int t    = threadIdx.x;
    const int wid  = t >> 5;
    const int b    = blockIdx.y;
    const int i0   = blockIdx.x * 128;

    if (wid == 0)
        asm volatile("tcgen05.alloc.cta_group::1.sync.aligned.shared::cta.b32 [%0], %1;"
                     :: "r"(sb + SM_TMEMPTR), "r"(256) : "memory");
    if (t == 0) {
        mbar_init(sb + SM_MBAR, 1);
        mbar_init(sb + SM_MBAR + 8, 1);
        mbar_init(sb + SM_MBAR + 16, 1);
    }
    float* Ays = (float*)(smem + SM_AYS);
    float* Ms  = (float*)(smem + SM_MS);
    if (t < 128) {
        float ay = g_Ay[b * NN + i0 + t];
        Ays[t] = ay;
        Ms[t]  = fmaxf(0.f, dec_f(g_maxAxEnc[b]) + ay);
    }

    // B prefetch mapping (hoisted offsets)
    const int bd   = t & 255;
    const int bsel = t >> 8;
    const __nv_bfloat16* hsrc =
        (bsel ? g_hTlo : g_hThi) + ((size_t)(b * DD + bd) << 12);
    uint32_t boff[4];
#pragma unroll
    for (int u = 0; u < 4; u++) boff[u] = sw128((uint32_t)(bd * 128 + bsel * 64 + u * 16));

    // A-gen mapping
    const int i1 = t >> 2;
    const int q  = t & 3;
    const int4* aRow = (const int4*)(adj + (size_t)b * NN * NN + (size_t)(i0 + i1) * NN) + q * 2;
    const float4* axp = (const float4*)(g_Ax + b * NN) + q * 2;
    const uint32_t ahoff = sw128((uint32_t)(i1 * 128 + q * 16));
    const uint32_t aloff = sw128((uint32_t)(i1 * 128 + 64 + q * 16));

    // prologue: B(0), B(1) prefetch; adj + ax regs for chunk 0
#pragma unroll
    for (int p = 0; p < 2; p++) {
        const __nv_bfloat16* src = hsrc + p * KC;
        const uint32_t base = sb + SM_BT + p * B_STRIDE;
#pragma unroll
        for (int u = 0; u < 4; u++) cpa16(base + boff[u], src + u * 8);
        asm volatile("cp.async.commit_group;" ::: "memory");
    }
    int4 cur0 = aRow[0], cur1 = aRow[1];
    float4 axc0 = axp[0], axc1 = axp[1];

    __syncthreads();
    uint32_t tmem;
    asm("ld.shared.b32 %0, [%1];" : "=r"(tmem) : "r"(sb + SM_TMEMPTR));

    const float ay_i = Ays[i1];
    const float M_i  = Ms[i1];
    float ssum = 0.f;

    for (int c = 0; c < NCHUNK; c++) {
        const int abuf = c % 3;
        const int bbuf = c % 5;

        // 3-deep: wait MMA(c-3) before reusing A buffer / letting B(c) slot rot
        if (c >= 3) mbar_wait(sb + SM_MBAR + 8 * abuf, (c / 3 - 1) & 1);

        // prefetch B(c+2) into slot (c+2)%5
        if (c + 2 < NCHUNK) {
            const __nv_bfloat16* src = hsrc + (c + 2) * KC;
            const uint32_t base = sb + SM_BT + ((c + 2) % 5) * B_STRIDE;
#pragma unroll
            for (int u = 0; u < 4; u++) cpa16(base + boff[u], src + u * 8);
        }
        asm volatile("cp.async.commit_group;" ::: "memory");

        // reg-prefetch adj + ax for chunk c+1
        int4 n0, n1; float4 axn0, axn1;
        if (c + 1 < NCHUNK) {
            n0 = aRow[(c + 1) * 8];
            n1 = aRow[(c + 1) * 8 + 1];
            axn0 = axp[(c + 1) * 8];
            axn1 = axp[(c + 1) * 8 + 1];
        }

        // ---- build A tile (P hi/lo) ----
        {
            const float axv[8] = {axc0.x, axc0.y, axc0.z, axc0.w,
                                  axc1.x, axc1.y, axc1.z, axc1.w};
            const int   am[8]  = {cur0.x, cur0.y, cur0.z, cur0.w,
                                  cur1.x, cur1.y, cur1.z, cur1.w};
            float pv[8];
#pragma unroll
            for (int v = 0; v < 8; v++) {
                float s = axv[v] + ay_i;
                float e = (s > 0.f) ? s : 0.2f * s;
                float p = (am[v] > 0) ? __expf(e - M_i) : 0.f;
                ssum += p;
                pv[v] = p;
            }
            uint32_t hw[4], lw[4];
#pragma unroll
            for (int w = 0; w < 4; w++) {
                uint32_t hi = bf2(pv[2 * w], pv[2 * w + 1]);
                float r0 = __uint_as_float(hi << 16);
                float r1 = __uint_as_float(hi & 0xffff0000u);
                hw[w] = hi;
                lw[w] = bf2(pv[2 * w] - r0, pv[2 * w + 1] - r1);
            }
            char* ab = smem + SM_AT + abuf * A_STRIDE;
            *(uint4*)(ab + ahoff) = make_uint4(hw[0], hw[1], hw[2], hw[3]);
            *(uint4*)(ab + aloff) = make_uint4(lw[0], lw[1], lw[2], lw[3]);
        }
        cur0 = n0; cur1 = n1; axc0 = axn0; axc1 = axn1;

        asm volatile("cp.async.wait_group 2;" ::: "memory");
        asm volatile("fence.proxy.async.shared::cta;" ::: "memory");
        __syncthreads();

        if (t == 0) {
            const uint64_t dA = smem_desc(sb + SM_AT + abuf * A_STRIDE);
            const uint64_t dB = smem_desc(sb + SM_BT + bbuf * B_STRIDE);
            mma_f16_ss(tmem, dA,     dB,     IDESC_VAL, c > 0 ? 1u : 0u);
            mma_f16_ss(tmem, dA + 2, dB + 2, IDESC_VAL, 1u);
            mma_f16_ss(tmem, dA,     dB + 4, IDESC_VAL, 1u);
            mma_f16_ss(tmem, dA + 2, dB + 6, IDESC_VAL, 1u);
            mma_f16_ss(tmem, dA + 4, dB,     IDESC_VAL, 1u);
            mma_f16_ss(tmem, dA + 6, dB + 2, IDESC_VAL, 1u);
            mma_commit(sb + SM_MBAR + 8 * abuf);
        }
    }

    // drain all 3 buffers
#pragma unroll
    for (int r = 0; r < 3; r++) {
        const int n = (NCHUNK + 2 - r) / 3;
        mbar_wait(sb + SM_MBAR + 8 * r, (n - 1) & 1);
    }
    asm volatile("tcgen05.fence::after_thread_sync;" ::: "memory");

    float* ssm = (float*)(smem + SM_SSM);
    ssm[t] = ssum;
    __syncthreads();

    // epilogue: x16 TMEM loads (lower register pressure)
    if (t < 128) {
        const int i = t;
        const float rs = 1.f / (ssm[4 * i] + ssm[4 * i + 1] + ssm[4 * i + 2] + ssm[4 * i + 3]);
        float* orow = out + (((size_t)(b * NN + i0 + i)) << 8);
#pragma unroll 1
        for (int cc = 0; cc < 16; cc++) {
            uint32_t r[16];
            asm volatile(
                "tcgen05.ld.sync.aligned.32x32b.x16.b32 "
                "{%0,%1,%2,%3,%4,%5,%6,%7,%8,%9,%10,%11,%12,%13,%14,%15}, [%16];"
                : "=r"(r[0]), "=r"(r[1]), "=r"(r[2]), "=r"(r[3]),
                  "=r"(r[4]), "=r"(r[5]), "=r"(r[6]), "=r"(r[7]),
                  "=r"(r[8]), "=r"(r[9]), "=r"(r[10]), "=r"(r[11]),
                  "=r"(r[12]), "=r"(r[13]), "=r"(r[14]), "=r"(r[15])
                : "r"(tmem + cc * 16));
            asm volatile("tcgen05.wait::ld.sync.aligned;" ::: "memory");
            float v[16];
#pragma unroll
            for (int k = 0; k < 16; k++) {
                float x = __uint_as_float(r[k]) * rs;
                v[k] = (x > 0.f) ? x : expm1f(x);
            }
#pragma unroll
            for (int k = 0; k < 4; k++)
                *(float4*)(orow + cc * 16 + k * 4) =
                    make_float4(v[k * 4], v[k * 4 + 1], v[k * 4 + 2], v[k * 4 + 3]);
        }
    }
    __syncthreads();
    if (wid == 0)
        asm volatile("tcgen05.dealloc.cta_group::1.sync.aligned.b32 %0, %1;"
                     :: "r"(tmem), "r"(256));

#else  // ---------------- fallback: fp32 CUDA-core path ------------------------
    float* pT  = (float*)(smem);                    // 128 j x 132
    float* Axs = (float*)(smem + 67584);
    float* Ays = (float*)(smem + 68096);
    float* Ms  = (float*)(smem + 68608);
    float* ssm = (float*)(smem + 69120);

    const int t  = threadIdx.x;
    const int b  = blockIdx.y;
    const int i0 = blockIdx.x * 128;

    if (t < 128) {
        float ay = g_Ay[b * NN + i0 + t];
        Ays[t] = ay;
        Ms[t]  = fmaxf(0.f, dec_f(g_maxAxEnc[b]) + ay);
    }
    __syncthreads();

    const int i1 = t >> 2;
    const int jc = (t & 3) * 32;
    const float ay_i = Ays[i1];
    const float M_i  = Ms[i1];
    const int ty = t >> 5;
    const int tx = t & 31;

    float acc[8][8];
#pragma unroll
    for (int i = 0; i < 8; i++)
#pragma unroll
        for (int j = 0; j < 8; j++) acc[i][j] = 0.f;
    float ssum = 0.f;

    const int* adjrow = adj + (size_t)b * NN * NN + (size_t)(i0 + i1) * NN + jc;

    for (int jt = 0; jt < 32; jt++) {
        const int j0 = jt * 128;
        if (t < 128) Axs[t] = g_Ax[b * NN + j0 + t];
        __syncthreads();

        const int4* ar = (const int4*)(adjrow + j0);
#pragma unroll
        for (int v = 0; v < 8; v++) {
            int4 a4 = ar[v];
            const int jj = jc + v * 4;
            const int am[4] = {a4.x, a4.y, a4.z, a4.w};
#pragma unroll
            for (int u = 0; u < 4; u++) {
                float s = Axs[jj + u] + ay_i;
                float e = (s > 0.f) ? s : 0.2f * s;
                float p = (am[u] > 0) ? __expf(e - M_i) : 0.f;
                ssum += p;
                pT[(jj + u) * 132 + i1] = p;
            }
        }
        __syncthreads();

        const float* hb = g_h + ((size_t)(b * NN + j0) << 8);
        for (int j = 0; j < 128; j++) {
            const float* hr = hb + ((size_t)j << 8);
            float4 h0 = *(const float4*)(hr + tx * 4);
            float4 h1 = *(const float4*)(hr + 128 + tx * 4);
            const float hh[8] = {h0.x, h0.y, h0.z, h0.w, h1.x, h1.y, h1.z, h1.w};
#pragma unroll
            for (int ii = 0; ii < 8; ii++) {
                float p = pT[j * 132 + ty * 8 + ii];
#pragma unroll
                for (int dd = 0; dd < 8; dd++) acc[ii][dd] += p * hh[dd];
            }
        }
        __syncthreads();
    }

    ssm[t] = ssum;
    __syncthreads();
#pragma unroll
    for (int ii = 0; ii < 8; ii++) {
        const int ie = ty * 8 + ii;
        float S = ssm[ie * 4] + ssm[ie * 4 + 1] + ssm[ie * 4 + 2] + ssm[ie * 4 + 3];
        float rs = 1.f / S;
        float v[8];
#pragma unroll
        for (int dd = 0; dd < 8; dd++) {
            float x = acc[ii][dd] * rs;
            v[dd] = (x > 0.f) ? x : expm1f(x);
        }
        float* pr = out + ((size_t)(b * NN + i0 + ie) << 8);
        *(float4*)(pr + tx * 4)       = make_float4(v[0], v[1], v[2], v[3]);
        *(float4*)(pr + 128 + tx * 4) = make_float4(v[4], v[5], v[6], v[7]);
    }
#endif
}

// ---------------- launch ------------------------------------------------------
extern "C" void kernel_launch(void* const* d_in, const int* in_sizes, int n_in,
                              void* d_out, int out_size) {
    const float* feat = (const float*)d_in[0];
    const int*   adj  = (const int*)d_in[1];
    const float* W    = (const float*)d_in[2];
    const float* a1   = (const float*)d_in[3];
    const float* a2   = (const float*)d_in[4];
    float* out = (float*)d_out;

    static bool attr_set = false;
    if (!attr_set) {
        cudaFuncSetAttribute(k_att, cudaFuncAttributeMaxDynamicSharedMemorySize, SMEM_TOTAL);
        cudaFuncSetAttribute(k_h_tc, cudaFuncAttributeMaxDynamicSharedMemorySize, SMEM_H_TOTAL);
        attr_set = true;
    }

    dim3 gW(4, 4);
    k_WT<<<gW, 256>>>(W);
    k_h_tc<<<BB * NN / 128, 512, SMEM_H_TOTAL>>>(feat, W, a1, a2);
    dim3 gT(64, 4, 4);
    k_hT<<<gT, 256>>>();
    dim3 grid(NN / 128, BB);
    k_att<<<grid, 512, SMEM_TOTAL>>>(adj, out);
}